// round 8
// baseline (speedup 1.0000x reference)
#include <cuda_runtime.h>
#include <math.h>
#include <float.h>

// Problem constants
#define B_ 8
#define T_ 512
#define D_ 256
#define S_ 64
#define P_ 1024
#define R_ 12
#define N1 (R_ * D_)   // 3072: columns of GEMM1 output, n = r*256 + e

// Scratch (device globals — no allocation allowed)
__device__ float g_pooled[B_ * S_ * D_];        // [bs][d]        512 KB
__device__ float g_L[B_ * S_ * 2 * R_];         // [bs][h*12+r]   48 KB
__device__ float g_T1[B_ * S_ * N1];            // [bs][r*256+e]  6.3 MB

// ---------------------------------------------------------------------------
// Kernel 1: ragged span max-pool + per-span linear terms.
// grid = B*S blocks, 256 threads (thread = feature d).
// Linear phase mapping: thread d holds pooled[d] and reads Wl rows d and
// 256+d (6 coalesced LDG.128, 12 lines/warp-load instead of 32), producing
// 24 partials; warp shuffle-reduce + small smem tree finish the dot.
// ---------------------------------------------------------------------------
__global__ __launch_bounds__(256)
void pool_kernel(const float* __restrict__ enc,
                 const float* __restrict__ Wl,   // [2D, R] row-major
                 const int* __restrict__ starts,
                 const int* __restrict__ lens) {
    __shared__ float red[8 * 24];

    int bs  = blockIdx.x;          // b*64 + s
    int b   = bs >> 6;
    int tid = threadIdx.x;
    int warp = tid >> 5, lane = tid & 31;

    int st = starts[bs];
    int en = st + lens[bs] + 1;    // exclusive, >= st+1
    if (en > T_) en = T_;

    const float* p = enc + ((size_t)b * T_ + st) * D_ + tid;
    float m = -FLT_MAX;
    for (int t = st; t < en; ++t) { m = fmaxf(m, *p); p += D_; }
    g_pooled[bs * D_ + tid] = m;

    // Wl rows for this d: row tid (head half) and row 256+tid (tail half),
    // each 12 consecutive floats (48 B, 16B-aligned since 48 | 16).
    float w[24];
    {
        const float4* w0 = (const float4*)(Wl + (size_t)tid * R_);
        const float4* w1 = (const float4*)(Wl + (size_t)(D_ + tid) * R_);
#pragma unroll
        for (int i = 0; i < 3; ++i) {
            float4 a = w0[i];
            w[i * 4 + 0] = a.x; w[i * 4 + 1] = a.y;
            w[i * 4 + 2] = a.z; w[i * 4 + 3] = a.w;
            float4 c = w1[i];
            w[12 + i * 4 + 0] = c.x; w[12 + i * 4 + 1] = c.y;
            w[12 + i * 4 + 2] = c.z; w[12 + i * 4 + 3] = c.w;
        }
    }

#pragma unroll
    for (int o = 0; o < 24; ++o) {
        float v = m * w[o];
#pragma unroll
        for (int off = 16; off; off >>= 1)
            v += __shfl_xor_sync(0xffffffffu, v, off);
        if (lane == 0) red[warp * 24 + o] = v;
    }
    __syncthreads();

    if (tid < 24) {
        float s = 0.f;
#pragma unroll
        for (int wp = 0; wp < 8; ++wp) s += red[wp * 24 + tid];
        g_L[bs * 24 + tid] = s;
    }
}

// ---------------------------------------------------------------------------
// Kernel 2: GEMM1  T1[(b,s), (r,e)] = sum_d pooled[(b,s), d] * Wb[r, d, e]
// BM=BN=64, BK=32, 256 threads, 4x4 scalar-FFMA micro-tile (proven R5 form).
// ---------------------------------------------------------------------------
__global__ __launch_bounds__(256)
void gemm1_kernel(const float* __restrict__ Wb) {
    __shared__ float As[32][64];   // [k][m]
    __shared__ float Bs[32][64];   // [k][n]

    int tid = threadIdx.x;
    int m0 = blockIdx.y * 64;
    int n0 = blockIdx.x * 64;
    int r  = n0 >> 8;
    int e0 = n0 & 255;
    const float* Bbase = Wb + (size_t)r * (D_ * D_) + e0;
    const float* A = g_pooled;

    int ty = tid >> 4, tx = tid & 15;          // 16x16 thread grid
    int ar = tid >> 3, ac = tid & 7;           // A loads
    int br = tid >> 4, bc = tid & 15;          // B loads

    float acc[4][4] = {};

    for (int k0 = 0; k0 < D_; k0 += 32) {
#pragma unroll
        for (int i = 0; i < 2; ++i) {
            int row = ar + i * 32;
            float4 v = *(const float4*)(A + (m0 + row) * D_ + k0 + ac * 4);
            As[ac * 4 + 0][row] = v.x;
            As[ac * 4 + 1][row] = v.y;
            As[ac * 4 + 2][row] = v.z;
            As[ac * 4 + 3][row] = v.w;
        }
#pragma unroll
        for (int i = 0; i < 2; ++i) {
            int row = br + i * 16;
            float4 v = *(const float4*)(Bbase + (size_t)(k0 + row) * D_ + bc * 4);
            *(float4*)&Bs[row][bc * 4] = v;
        }
        __syncthreads();

#pragma unroll
        for (int kk = 0; kk < 32; ++kk) {
            float4 a = *(float4*)&As[kk][ty * 4];
            float4 b = *(float4*)&Bs[kk][tx * 4];
            float av[4] = {a.x, a.y, a.z, a.w};
            float bv[4] = {b.x, b.y, b.z, b.w};
#pragma unroll
            for (int i = 0; i < 4; ++i)
#pragma unroll
                for (int j = 0; j < 4; ++j)
                    acc[i][j] += av[i] * bv[j];
        }
        __syncthreads();
    }

#pragma unroll
    for (int i = 0; i < 4; ++i) {
        float4 v = make_float4(acc[i][0], acc[i][1], acc[i][2], acc[i][3]);
        *(float4*)(g_T1 + (size_t)(m0 + ty * 4 + i) * N1 + n0 + tx * 4) = v;
    }
}

// ---------------------------------------------------------------------------
// Kernel 3: GEMM2 + fused score.
// One block per (b,r): G[s,t] = sum_e T1[b,s,r*256+e] * pooled[b,t,e]
// (64x64x256, proven 4x4 scalar micro-tile). The G tile is parked in smem,
// then the same block gathers its batch's 1024 pairs and writes out[b,p,r]
// directly (unique (b,r) per block -> no atomics). Removes the score kernel
// and the 1.6 MB G round-trip. Smem tiles use pitch 68 (rows stay 16B-aligned
// for LDS.128; store conflicts drop 4-way -> 2-way).
// ---------------------------------------------------------------------------
__global__ __launch_bounds__(256)
void gemm2_kernel(const float* __restrict__ bias,
                  const int* __restrict__ ph,
                  const int* __restrict__ pt,
                  float* __restrict__ out) {
    int bid = blockIdx.x;                 // b*12 + r
    int b = bid / R_;
    int r = bid - b * R_;

    __shared__ float As[64][68];          // [e][s]  17.4 KB
    __shared__ float Bs[64][68];          // [e][t]  17.4 KB
    __shared__ float sg[64 * 64];         // G tile  16 KB

    int tid = threadIdx.x;
    int ty = tid >> 4, tx = tid & 15;
    int lr = tid >> 2;                    // row 0..63
    int lc = tid & 3;                     // base float4 col group

    const float* Ab = g_T1 + (size_t)b * S_ * N1 + r * D_;   // row s: +s*N1
    const float* Bb = g_pooled + (size_t)b * S_ * D_;        // row t: +t*256

    float acc[4][4] = {};

    for (int e0 = 0; e0 < D_; e0 += 64) {
#pragma unroll
        for (int i = 0; i < 4; ++i) {
            int cg = lc + 4 * i;          // 0..15
            float4 v = *(const float4*)(Ab + (size_t)lr * N1 + e0 + cg * 4);
            As[cg * 4 + 0][lr] = v.x;
            As[cg * 4 + 1][lr] = v.y;
            As[cg * 4 + 2][lr] = v.z;
            As[cg * 4 + 3][lr] = v.w;
            float4 w = *(const float4*)(Bb + lr * D_ + e0 + cg * 4);
            Bs[cg * 4 + 0][lr] = w.x;
            Bs[cg * 4 + 1][lr] = w.y;
            Bs[cg * 4 + 2][lr] = w.z;
            Bs[cg * 4 + 3][lr] = w.w;
        }
        __syncthreads();

#pragma unroll
        for (int kk = 0; kk < 64; ++kk) {
            float4 a = *(float4*)&As[kk][ty * 4];
            float4 bv = *(float4*)&Bs[kk][tx * 4];
            float av[4] = {a.x, a.y, a.z, a.w};
            float bw[4] = {bv.x, bv.y, bv.z, bv.w};
#pragma unroll
            for (int i = 0; i < 4; ++i)
#pragma unroll
                for (int j = 0; j < 4; ++j)
                    acc[i][j] += av[i] * bw[j];
        }
        __syncthreads();
    }

    // Park G tile in smem, then fused pair-score gather.
#pragma unroll
    for (int i = 0; i < 4; ++i) {
        *(float4*)&sg[(ty * 4 + i) * 64 + tx * 4] =
            make_float4(acc[i][0], acc[i][1], acc[i][2], acc[i][3]);
    }
    __syncthreads();

    float bv = bias[r];
    const float* Lb = g_L + (size_t)b * S_ * (2 * R_);
    const int* phb = ph + (b << 10);
    const int* ptb = pt + (b << 10);
    for (int p = tid; p < P_; p += 256) {
        int h = phb[p];
        int t = ptb[p];
        float sc = sg[h * 64 + t] + Lb[h * 24 + r] + Lb[t * 24 + 12 + r] + bv;
        out[(size_t)((b << 10) + p) * R_ + r] = 1.f / (1.f + __expf(-sc));
    }
}

// ---------------------------------------------------------------------------
// Launch.  Inputs in metadata order:
// 0 encoded f32 [8,512,256]   1 W_linear f32 [512,12]   2 b_linear f32 [12]
// 3 W_bilinear f32 [12,256,256]
// 4 span_starts i32 [8,64]    5 span_lens i32 [8,64]
// 6 pair_head i32 [8,1024]    7 pair_tail i32 [8,1024]
// Output f32 [8,1024,12].
// ---------------------------------------------------------------------------
extern "C" void kernel_launch(void* const* d_in, const int* in_sizes, int n_in,
                              void* d_out, int out_size) {
    const float* enc = (const float*)d_in[0];
    const float* Wl  = (const float*)d_in[1];
    const float* bl  = (const float*)d_in[2];
    const float* Wb  = (const float*)d_in[3];
    const int* sst   = (const int*)d_in[4];
    const int* sln   = (const int*)d_in[5];
    const int* ph    = (const int*)d_in[6];
    const int* pt    = (const int*)d_in[7];
    float* out = (float*)d_out;

    pool_kernel<<<B_ * S_, 256>>>(enc, Wl, sst, sln);
    gemm1_kernel<<<dim3(N1 / 64, (B_ * S_) / 64), 256>>>(Wb);
    gemm2_kernel<<<B_ * R_, 256>>>(bl, ph, pt, out);
}

// round 10
// speedup vs baseline: 1.5981x; 1.5981x over previous
#include <cuda_runtime.h>
#include <math.h>
#include <float.h>

// Problem constants
#define B_ 8
#define T_ 512
#define D_ 256
#define S_ 64
#define P_ 1024
#define R_ 12
#define N1 (R_ * D_)   // 3072: columns of GEMM1 output, n = r*256 + e

// Scratch (device globals — no allocation allowed)
__device__ float g_pooled[B_ * S_ * D_];        // [bs][d]        512 KB
__device__ float g_L[B_ * S_ * 2 * R_];         // [bs][h*12+r]   48 KB
__device__ float g_T1[B_ * S_ * N1];            // [bs][r*256+e]  6.3 MB
__device__ float g_G[B_ * R_ * S_ * S_];        // [(b*12+r)][s][t] 1.6 MB

// ---------------------------------------------------------------------------
// Kernel 1: ragged span max-pool + per-span linear terms. (exact R5 form)
// ---------------------------------------------------------------------------
__global__ __launch_bounds__(256)
void pool_kernel(const float* __restrict__ enc,
                 const float* __restrict__ Wl,   // [2D, R] row-major
                 const int* __restrict__ starts,
                 const int* __restrict__ lens) {
    int bs  = blockIdx.x;          // b*64 + s
    int b   = bs >> 6;
    int tid = threadIdx.x;

    int st = starts[bs];
    int en = st + lens[bs] + 1;    // exclusive, >= st+1
    if (en > T_) en = T_;

    const float* p = enc + ((size_t)b * T_ + st) * D_ + tid;
    float m = -FLT_MAX;
    for (int t = st; t < en; ++t) { m = fmaxf(m, *p); p += D_; }
    g_pooled[bs * D_ + tid] = m;

    __shared__ float sp[D_];
    sp[tid] = m;
    __syncthreads();

    int warp = tid >> 5, lane = tid & 31;
#pragma unroll
    for (int j = 0; j < 3; ++j) {
        int o = warp * 3 + j;          // 0..23
        int h = o / R_;
        int r = o - h * R_;
        float sum = 0.f;
        for (int d = lane; d < D_; d += 32)
            sum += sp[d] * Wl[(h * D_ + d) * R_ + r];
#pragma unroll
        for (int off = 16; off; off >>= 1)
            sum += __shfl_xor_sync(0xffffffffu, sum, off);
        if (lane == 0) g_L[bs * (2 * R_) + o] = sum;
    }
}

// ---------------------------------------------------------------------------
// Kernel 2: GEMM1  T1[(b,s), (r,e)] = sum_d pooled[(b,s), d] * Wb[r, d, e]
// BM=BN=64, BK=32, 256 threads, 4x4 scalar-FFMA micro-tile (R5 mainloop),
// now software-pipelined: double-buffered smem, cp.async for the B tile,
// register prefetch + STS for the A tile (transposed), ONE barrier / chunk.
// ---------------------------------------------------------------------------
__global__ __launch_bounds__(256)
void gemm1_kernel(const float* __restrict__ Wb) {
    __shared__ float As[2][32][64];   // [stage][k][m]
    __shared__ float Bs[2][32][64];   // [stage][k][n]

    int tid = threadIdx.x;
    int m0 = blockIdx.y * 64;
    int n0 = blockIdx.x * 64;
    int r  = n0 >> 8;
    int e0 = n0 & 255;
    const float* Bbase = Wb + (size_t)r * (D_ * D_) + e0;
    const float* A = g_pooled;

    int ty = tid >> 4, tx = tid & 15;          // 16x16 thread grid
    int ar = tid >> 3, ac = tid & 7;           // A loads
    int br = tid >> 4, bc = tid & 15;          // B loads

    unsigned bs_base = (unsigned)__cvta_generic_to_shared(&Bs[0][0][0]);

    float acc[4][4] = {};
    float4 pa[2];

    // ---- prologue: stage 0 ----
#pragma unroll
    for (int i = 0; i < 2; ++i)
        pa[i] = *(const float4*)(A + (size_t)(m0 + ar + i * 32) * D_ + ac * 4);
#pragma unroll
    for (int i = 0; i < 2; ++i) {
        unsigned dst = bs_base + (unsigned)(((br + i * 16) * 64 + bc * 4) * 4);
        const float* src = Bbase + (size_t)(br + i * 16) * D_ + bc * 4;
        asm volatile("cp.async.cg.shared.global [%0], [%1], 16;"
                     :: "r"(dst), "l"(src) : "memory");
    }
    asm volatile("cp.async.commit_group;" ::: "memory");
#pragma unroll
    for (int i = 0; i < 2; ++i) {
        int row = ar + i * 32;
        As[0][ac * 4 + 0][row] = pa[i].x;
        As[0][ac * 4 + 1][row] = pa[i].y;
        As[0][ac * 4 + 2][row] = pa[i].z;
        As[0][ac * 4 + 3][row] = pa[i].w;
    }
    asm volatile("cp.async.wait_group 0;" ::: "memory");
    __syncthreads();

    // ---- main loop: 8 chunks, one barrier each ----
#pragma unroll
    for (int it = 0; it < 8; ++it) {
        int c = it & 1;
        if (it < 7) {
            int k0 = (it + 1) * 32;
#pragma unroll
            for (int i = 0; i < 2; ++i)
                pa[i] = *(const float4*)(A + (size_t)(m0 + ar + i * 32) * D_ + k0 + ac * 4);
#pragma unroll
            for (int i = 0; i < 2; ++i) {
                unsigned dst = bs_base +
                    (unsigned)((((1 - c) * 32 + br + i * 16) * 64 + bc * 4) * 4);
                const float* src = Bbase + (size_t)(k0 + br + i * 16) * D_ + bc * 4;
                asm volatile("cp.async.cg.shared.global [%0], [%1], 16;"
                             :: "r"(dst), "l"(src) : "memory");
            }
            asm volatile("cp.async.commit_group;" ::: "memory");
        }

#pragma unroll
        for (int kk = 0; kk < 32; ++kk) {
            float4 a = *(float4*)&As[c][kk][ty * 4];
            float4 b = *(float4*)&Bs[c][kk][tx * 4];
            float av[4] = {a.x, a.y, a.z, a.w};
            float bv[4] = {b.x, b.y, b.z, b.w};
#pragma unroll
            for (int i = 0; i < 4; ++i)
#pragma unroll
                for (int j = 0; j < 4; ++j)
                    acc[i][j] += av[i] * bv[j];
        }

        if (it < 7) {
#pragma unroll
            for (int i = 0; i < 2; ++i) {
                int row = ar + i * 32;
                As[1 - c][ac * 4 + 0][row] = pa[i].x;
                As[1 - c][ac * 4 + 1][row] = pa[i].y;
                As[1 - c][ac * 4 + 2][row] = pa[i].z;
                As[1 - c][ac * 4 + 3][row] = pa[i].w;
            }
            asm volatile("cp.async.wait_group 0;" ::: "memory");
        }
        __syncthreads();
    }

#pragma unroll
    for (int i = 0; i < 4; ++i) {
        float4 v = make_float4(acc[i][0], acc[i][1], acc[i][2], acc[i][3]);
        *(float4*)(g_T1 + (size_t)(m0 + ty * 4 + i) * N1 + n0 + tx * 4) = v;
    }
}

// ---------------------------------------------------------------------------
// Kernel 3: GEMM2 (batched NT)  G[b,r,s,t] = sum_e T1[b,s,r*256+e]*pooled[b,t,e]
// R5 structure (96 blocks, 64x64x256, 4x4 micro-tile), with register prefetch:
// next e-chunk's global loads issue before the compute loop and are stored
// after it, hiding global latency under the 64-step FMA loop.
// ---------------------------------------------------------------------------
__global__ __launch_bounds__(256)
void gemm2_kernel() {
    int bid = blockIdx.x;                 // b*12 + r
    int b = bid / R_;
    int r = bid - b * R_;

    __shared__ float As[64][64];          // [e][s]
    __shared__ float Bs[64][64];          // [e][t]

    int tid = threadIdx.x;
    int ty = tid >> 4, tx = tid & 15;
    int lr = tid >> 2;                    // row 0..63
    int lc = tid & 3;                     // base float4 col group

    const float* Ab = g_T1 + (size_t)b * S_ * N1 + r * D_;   // row s: +s*N1
    const float* Bb = g_pooled + (size_t)b * S_ * D_;        // row t: +t*256

    float acc[4][4] = {};
    float4 va[4], vb[4];

    // prologue: e0 = 0
#pragma unroll
    for (int i = 0; i < 4; ++i) {
        int cg = lc + 4 * i;
        va[i] = *(const float4*)(Ab + (size_t)lr * N1 + cg * 4);
        vb[i] = *(const float4*)(Bb + lr * D_ + cg * 4);
    }

#pragma unroll
    for (int it = 0; it < 4; ++it) {
        // store current regs (transposed)
#pragma unroll
        for (int i = 0; i < 4; ++i) {
            int cg = lc + 4 * i;
            As[cg * 4 + 0][lr] = va[i].x;
            As[cg * 4 + 1][lr] = va[i].y;
            As[cg * 4 + 2][lr] = va[i].z;
            As[cg * 4 + 3][lr] = va[i].w;
            Bs[cg * 4 + 0][lr] = vb[i].x;
            Bs[cg * 4 + 1][lr] = vb[i].y;
            Bs[cg * 4 + 2][lr] = vb[i].z;
            Bs[cg * 4 + 3][lr] = vb[i].w;
        }
        __syncthreads();

        if (it < 3) {
            int e0 = (it + 1) * 64;
#pragma unroll
            for (int i = 0; i < 4; ++i) {
                int cg = lc + 4 * i;
                va[i] = *(const float4*)(Ab + (size_t)lr * N1 + e0 + cg * 4);
                vb[i] = *(const float4*)(Bb + lr * D_ + e0 + cg * 4);
            }
        }

#pragma unroll
        for (int kk = 0; kk < 64; ++kk) {
            float4 a = *(float4*)&As[kk][ty * 4];
            float4 bv = *(float4*)&Bs[kk][tx * 4];
            float av[4] = {a.x, a.y, a.z, a.w};
            float bw[4] = {bv.x, bv.y, bv.z, bv.w};
#pragma unroll
            for (int i = 0; i < 4; ++i)
#pragma unroll
                for (int j = 0; j < 4; ++j)
                    acc[i][j] += av[i] * bw[j];
        }
        __syncthreads();
    }

#pragma unroll
    for (int i = 0; i < 4; ++i) {
        float4 v = make_float4(acc[i][0], acc[i][1], acc[i][2], acc[i][3]);
        *(float4*)(g_G + (size_t)bid * (S_ * S_) + (ty * 4 + i) * S_ + tx * 4) = v;
    }
}

// ---------------------------------------------------------------------------
// Kernel 4: final pair scores + sigmoid. (exact R5 form, __expf)
// ---------------------------------------------------------------------------
__global__ __launch_bounds__(256)
void score_kernel(const float* __restrict__ bias,
                  const int* __restrict__ ph,
                  const int* __restrict__ pt,
                  float* __restrict__ out) {
    int g = blockIdx.x * blockDim.x + threadIdx.x;
    if (g >= B_ * P_ * R_) return;
    int r  = g % R_;
    int bp = g / R_;          // b*1024 + p
    int b  = bp >> 10;

    int h = ph[bp];
    int t = pt[bp];

    float sc = g_L[(b * S_ + h) * (2 * R_) + r]
             + g_L[(b * S_ + t) * (2 * R_) + R_ + r]
             + bias[r]
             + g_G[(((size_t)b * R_ + r) * S_ + h) * S_ + t];
    out[g] = 1.f / (1.f + __expf(-sc));
}

// ---------------------------------------------------------------------------
// Launch.  Inputs in metadata order:
// 0 encoded f32 [8,512,256]   1 W_linear f32 [512,12]   2 b_linear f32 [12]
// 3 W_bilinear f32 [12,256,256]
// 4 span_starts i32 [8,64]    5 span_lens i32 [8,64]
// 6 pair_head i32 [8,1024]    7 pair_tail i32 [8,1024]
// Output f32 [8,1024,12].
// ---------------------------------------------------------------------------
extern "C" void kernel_launch(void* const* d_in, const int* in_sizes, int n_in,
                              void* d_out, int out_size) {
    const float* enc = (const float*)d_in[0];
    const float* Wl  = (const float*)d_in[1];
    const float* bl  = (const float*)d_in[2];
    const float* Wb  = (const float*)d_in[3];
    const int* sst   = (const int*)d_in[4];
    const int* sln   = (const int*)d_in[5];
    const int* ph    = (const int*)d_in[6];
    const int* pt    = (const int*)d_in[7];
    float* out = (float*)d_out;

    pool_kernel<<<B_ * S_, 256>>>(enc, Wl, sst, sln);
    gemm1_kernel<<<dim3(N1 / 64, (B_ * S_) / 64), 256>>>(Wb);
    gemm2_kernel<<<B_ * R_, 256>>>();
    score_kernel<<<(B_ * P_ * R_ + 255) / 256, 256>>>(bl, ph, pt, out);
}

// round 11
// speedup vs baseline: 1.6555x; 1.0359x over previous
#include <cuda_runtime.h>
#include <math.h>
#include <float.h>

// Problem constants
#define B_ 8
#define T_ 512
#define D_ 256
#define S_ 64
#define P_ 1024
#define R_ 12
#define N1 (R_ * D_)   // 3072: columns of GEMM1 output, n = r*256 + e

// Scratch (device globals — no allocation allowed)
__device__ float g_pooled[B_ * S_ * D_];        // [bs][d]        512 KB
__device__ float g_L[B_ * S_ * 2 * R_];         // [bs][h*12+r]   48 KB
__device__ float g_T1[B_ * S_ * N1];            // [bs][r*256+e]  6.3 MB

// ---------------------------------------------------------------------------
// Kernel 1: ragged span max-pool + per-span linear terms. (proven R5/R10 form)
// ---------------------------------------------------------------------------
__global__ __launch_bounds__(256)
void pool_kernel(const float* __restrict__ enc,
                 const float* __restrict__ Wl,   // [2D, R] row-major
                 const int* __restrict__ starts,
                 const int* __restrict__ lens) {
    int bs  = blockIdx.x;          // b*64 + s
    int b   = bs >> 6;
    int tid = threadIdx.x;

    int st = starts[bs];
    int en = st + lens[bs] + 1;    // exclusive, >= st+1
    if (en > T_) en = T_;

    const float* p = enc + ((size_t)b * T_ + st) * D_ + tid;
    float m = -FLT_MAX;
    for (int t = st; t < en; ++t) { m = fmaxf(m, *p); p += D_; }
    g_pooled[bs * D_ + tid] = m;

    __shared__ float sp[D_];
    sp[tid] = m;
    __syncthreads();

    int warp = tid >> 5, lane = tid & 31;
#pragma unroll
    for (int j = 0; j < 3; ++j) {
        int o = warp * 3 + j;          // 0..23
        int h = o / R_;
        int r = o - h * R_;
        float sum = 0.f;
        for (int d = lane; d < D_; d += 32)
            sum += sp[d] * Wl[(h * D_ + d) * R_ + r];
#pragma unroll
        for (int off = 16; off; off >>= 1)
            sum += __shfl_xor_sync(0xffffffffu, sum, off);
        if (lane == 0) g_L[bs * (2 * R_) + o] = sum;
    }
}

// ---------------------------------------------------------------------------
// Kernel 2: GEMM1  T1[(b,s), (r,e)] = sum_d pooled[(b,s), d] * Wb[r, d, e]
// BM=BN=64, BK=32, 256 threads, 4x4 scalar-FFMA micro-tile, software-
// pipelined (double-buffered smem, cp.async B tile, reg-prefetch A tile,
// one barrier per chunk). Byte-identical to the R10 WIN version.
// ---------------------------------------------------------------------------
__global__ __launch_bounds__(256)
void gemm1_kernel(const float* __restrict__ Wb) {
    __shared__ float As[2][32][64];   // [stage][k][m]
    __shared__ float Bs[2][32][64];   // [stage][k][n]

    int tid = threadIdx.x;
    int m0 = blockIdx.y * 64;
    int n0 = blockIdx.x * 64;
    int r  = n0 >> 8;
    int e0 = n0 & 255;
    const float* Bbase = Wb + (size_t)r * (D_ * D_) + e0;
    const float* A = g_pooled;

    int ty = tid >> 4, tx = tid & 15;          // 16x16 thread grid
    int ar = tid >> 3, ac = tid & 7;           // A loads
    int br = tid >> 4, bc = tid & 15;          // B loads

    unsigned bs_base = (unsigned)__cvta_generic_to_shared(&Bs[0][0][0]);

    float acc[4][4] = {};
    float4 pa[2];

    // ---- prologue: stage 0 ----
#pragma unroll
    for (int i = 0; i < 2; ++i)
        pa[i] = *(const float4*)(A + (size_t)(m0 + ar + i * 32) * D_ + ac * 4);
#pragma unroll
    for (int i = 0; i < 2; ++i) {
        unsigned dst = bs_base + (unsigned)(((br + i * 16) * 64 + bc * 4) * 4);
        const float* src = Bbase + (size_t)(br + i * 16) * D_ + bc * 4;
        asm volatile("cp.async.cg.shared.global [%0], [%1], 16;"
                     :: "r"(dst), "l"(src) : "memory");
    }
    asm volatile("cp.async.commit_group;" ::: "memory");
#pragma unroll
    for (int i = 0; i < 2; ++i) {
        int row = ar + i * 32;
        As[0][ac * 4 + 0][row] = pa[i].x;
        As[0][ac * 4 + 1][row] = pa[i].y;
        As[0][ac * 4 + 2][row] = pa[i].z;
        As[0][ac * 4 + 3][row] = pa[i].w;
    }
    asm volatile("cp.async.wait_group 0;" ::: "memory");
    __syncthreads();

    // ---- main loop: 8 chunks, one barrier each ----
#pragma unroll
    for (int it = 0; it < 8; ++it) {
        int c = it & 1;
        if (it < 7) {
            int k0 = (it + 1) * 32;
#pragma unroll
            for (int i = 0; i < 2; ++i)
                pa[i] = *(const float4*)(A + (size_t)(m0 + ar + i * 32) * D_ + k0 + ac * 4);
#pragma unroll
            for (int i = 0; i < 2; ++i) {
                unsigned dst = bs_base +
                    (unsigned)((((1 - c) * 32 + br + i * 16) * 64 + bc * 4) * 4);
                const float* src = Bbase + (size_t)(k0 + br + i * 16) * D_ + bc * 4;
                asm volatile("cp.async.cg.shared.global [%0], [%1], 16;"
                             :: "r"(dst), "l"(src) : "memory");
            }
            asm volatile("cp.async.commit_group;" ::: "memory");
        }

#pragma unroll
        for (int kk = 0; kk < 32; ++kk) {
            float4 a = *(float4*)&As[c][kk][ty * 4];
            float4 b = *(float4*)&Bs[c][kk][tx * 4];
            float av[4] = {a.x, a.y, a.z, a.w};
            float bv[4] = {b.x, b.y, b.z, b.w};
#pragma unroll
            for (int i = 0; i < 4; ++i)
#pragma unroll
                for (int j = 0; j < 4; ++j)
                    acc[i][j] += av[i] * bv[j];
        }

        if (it < 7) {
#pragma unroll
            for (int i = 0; i < 2; ++i) {
                int row = ar + i * 32;
                As[1 - c][ac * 4 + 0][row] = pa[i].x;
                As[1 - c][ac * 4 + 1][row] = pa[i].y;
                As[1 - c][ac * 4 + 2][row] = pa[i].z;
                As[1 - c][ac * 4 + 3][row] = pa[i].w;
            }
            asm volatile("cp.async.wait_group 0;" ::: "memory");
        }
        __syncthreads();
    }

#pragma unroll
    for (int i = 0; i < 4; ++i) {
        float4 v = make_float4(acc[i][0], acc[i][1], acc[i][2], acc[i][3]);
        *(float4*)(g_T1 + (size_t)(m0 + ty * 4 + i) * N1 + n0 + tx * 4) = v;
    }
}

// ---------------------------------------------------------------------------
// Kernel 3: GEMM2 + fused score epilogue.
// R10 mainloop byte-identical (96 blocks, 64x64x256, 4x4 micro-tile, reg
// prefetch). NEW: the 64x64 G tile is parked in smem (reusing As storage —
// no extra smem) and the same block gathers its batch's 1024 pairs, writing
// out[b,p,r] directly (unique (b,r) per block -> no atomics). Deletes the
// score kernel and the 1.6 MB g_G round-trip.
// ---------------------------------------------------------------------------
__global__ __launch_bounds__(256)
void gemm2_kernel(const float* __restrict__ bias,
                  const int* __restrict__ ph,
                  const int* __restrict__ pt,
                  float* __restrict__ out) {
    int bid = blockIdx.x;                 // b*12 + r
    int b = bid / R_;
    int r = bid - b * R_;

    __shared__ float As[64][64];          // [e][s]; reused as G tile in epilogue
    __shared__ float Bs[64][64];          // [e][t]

    int tid = threadIdx.x;
    int ty = tid >> 4, tx = tid & 15;
    int lr = tid >> 2;                    // row 0..63
    int lc = tid & 3;                     // base float4 col group

    const float* Ab = g_T1 + (size_t)b * S_ * N1 + r * D_;   // row s: +s*N1
    const float* Bb = g_pooled + (size_t)b * S_ * D_;        // row t: +t*256

    float acc[4][4] = {};
    float4 va[4], vb[4];

    // prologue: e0 = 0
#pragma unroll
    for (int i = 0; i < 4; ++i) {
        int cg = lc + 4 * i;
        va[i] = *(const float4*)(Ab + (size_t)lr * N1 + cg * 4);
        vb[i] = *(const float4*)(Bb + lr * D_ + cg * 4);
    }

#pragma unroll
    for (int it = 0; it < 4; ++it) {
        // store current regs (transposed)
#pragma unroll
        for (int i = 0; i < 4; ++i) {
            int cg = lc + 4 * i;
            As[cg * 4 + 0][lr] = va[i].x;
            As[cg * 4 + 1][lr] = va[i].y;
            As[cg * 4 + 2][lr] = va[i].z;
            As[cg * 4 + 3][lr] = va[i].w;
            Bs[cg * 4 + 0][lr] = vb[i].x;
            Bs[cg * 4 + 1][lr] = vb[i].y;
            Bs[cg * 4 + 2][lr] = vb[i].z;
            Bs[cg * 4 + 3][lr] = vb[i].w;
        }
        __syncthreads();

        if (it < 3) {
            int e0 = (it + 1) * 64;
#pragma unroll
            for (int i = 0; i < 4; ++i) {
                int cg = lc + 4 * i;
                va[i] = *(const float4*)(Ab + (size_t)lr * N1 + e0 + cg * 4);
                vb[i] = *(const float4*)(Bb + lr * D_ + e0 + cg * 4);
            }
        }

#pragma unroll
        for (int kk = 0; kk < 64; ++kk) {
            float4 a = *(float4*)&As[kk][ty * 4];
            float4 bv = *(float4*)&Bs[kk][tx * 4];
            float av[4] = {a.x, a.y, a.z, a.w};
            float bw[4] = {bv.x, bv.y, bv.z, bv.w};
#pragma unroll
            for (int i = 0; i < 4; ++i)
#pragma unroll
                for (int j = 0; j < 4; ++j)
                    acc[i][j] += av[i] * bw[j];
        }
        __syncthreads();
    }

    // Park G tile in smem (As storage is free after the last barrier).
    float* sg = &As[0][0];
#pragma unroll
    for (int i = 0; i < 4; ++i) {
        *(float4*)&sg[(ty * 4 + i) * 64 + tx * 4] =
            make_float4(acc[i][0], acc[i][1], acc[i][2], acc[i][3]);
    }
    __syncthreads();

    // Fused pair-score gather: 1024 pairs / 256 threads = 4 each.
    float bv = bias[r];
    const float* Lb = g_L + (size_t)b * S_ * (2 * R_);
    const int* phb = ph + (b << 10);
    const int* ptb = pt + (b << 10);
#pragma unroll
    for (int i = 0; i < 4; ++i) {
        int p = tid + i * 256;
        int h = phb[p];
        int t = ptb[p];
        float sc = sg[h * 64 + t] + Lb[h * 24 + r] + Lb[t * 24 + 12 + r] + bv;
        out[(size_t)((b << 10) + p) * R_ + r] = 1.f / (1.f + __expf(-sc));
    }
}

// ---------------------------------------------------------------------------
// Launch.  Inputs in metadata order:
// 0 encoded f32 [8,512,256]   1 W_linear f32 [512,12]   2 b_linear f32 [12]
// 3 W_bilinear f32 [12,256,256]
// 4 span_starts i32 [8,64]    5 span_lens i32 [8,64]
// 6 pair_head i32 [8,1024]    7 pair_tail i32 [8,1024]
// Output f32 [8,1024,12].
// ---------------------------------------------------------------------------
extern "C" void kernel_launch(void* const* d_in, const int* in_sizes, int n_in,
                              void* d_out, int out_size) {
    const float* enc = (const float*)d_in[0];
    const float* Wl  = (const float*)d_in[1];
    const float* bl  = (const float*)d_in[2];
    const float* Wb  = (const float*)d_in[3];
    const int* sst   = (const int*)d_in[4];
    const int* sln   = (const int*)d_in[5];
    const int* ph    = (const int*)d_in[6];
    const int* pt    = (const int*)d_in[7];
    float* out = (float*)d_out;

    pool_kernel<<<B_ * S_, 256>>>(enc, Wl, sst, sln);
    gemm1_kernel<<<dim3(N1 / 64, (B_ * S_) / 64), 256>>>(Wb);
    gemm2_kernel<<<B_ * R_, 256>>>(bl, ph, pt, out);
}

// round 12
// speedup vs baseline: 1.6630x; 1.0045x over previous
#include <cuda_runtime.h>
#include <math.h>
#include <float.h>

// Problem constants
#define B_ 8
#define T_ 512
#define D_ 256
#define S_ 64
#define P_ 1024
#define R_ 12
#define N1 (R_ * D_)   // 3072: columns of GEMM1 output, n = r*256 + e

// Scratch (device globals — no allocation allowed)
__device__ float g_pooled[B_ * S_ * D_];        // [bs][d]        512 KB
__device__ float g_L[B_ * S_ * 2 * R_];         // [bs][h*12+r]   48 KB
__device__ float g_T1[B_ * S_ * N1];            // [bs][r*256+e]  6.3 MB

// ---------------------------------------------------------------------------
// Kernel 1: ragged span max-pool + per-span linear terms.
// Max phase: thread = feature d (as in the proven R5/R11 form).
// Linear phase REMAPPED: lane = output o (24 active), warp w sweeps its 32
// d-values. For fixed d, lanes read two 48B contiguous Wl segments -> 2-3
// lines per warp-load (was 32). No shuffles; cross-warp smem tree finishes.
// ---------------------------------------------------------------------------
__global__ __launch_bounds__(256)
void pool_kernel(const float* __restrict__ enc,
                 const float* __restrict__ Wl,   // [2D, R] row-major
                 const int* __restrict__ starts,
                 const int* __restrict__ lens) {
    __shared__ float sp[D_];
    __shared__ float red[8 * 24];

    int bs  = blockIdx.x;          // b*64 + s
    int b   = bs >> 6;
    int tid = threadIdx.x;
    int warp = tid >> 5, lane = tid & 31;

    int st = starts[bs];
    int en = st + lens[bs] + 1;    // exclusive, >= st+1
    if (en > T_) en = T_;

    const float* p = enc + ((size_t)b * T_ + st) * D_ + tid;
    float m = -FLT_MAX;
    for (int t = st; t < en; ++t) { m = fmaxf(m, *p); p += D_; }
    g_pooled[bs * D_ + tid] = m;
    sp[tid] = m;
    __syncthreads();

    // lane o = h*12 + r (o < 24 active): sum over this warp's 32 d-values of
    // sp[d] * Wl[h*3072 + d*12 + r].
    if (lane < 24) {
        int h = (lane >= 12);
        int r = lane - h * 12;
        const float* wp = Wl + h * (D_ * R_) + r;
        int d0 = warp * 32;
        float sum = 0.f;
#pragma unroll
        for (int dd = 0; dd < 32; ++dd) {
            int d = d0 + dd;
            sum += sp[d] * wp[d * R_];
        }
        red[warp * 24 + lane] = sum;
    }
    __syncthreads();

    if (tid < 24) {
        float s = 0.f;
#pragma unroll
        for (int wp8 = 0; wp8 < 8; ++wp8) s += red[wp8 * 24 + tid];
        g_L[bs * (2 * R_) + tid] = s;
    }
}

// ---------------------------------------------------------------------------
// Kernel 2: GEMM1  T1[(b,s), (r,e)] = sum_d pooled[(b,s), d] * Wb[r, d, e]
// BM=BN=64, BK=32, 256 threads, 4x4 scalar-FFMA micro-tile, software-
// pipelined (double-buffered smem, cp.async B tile, reg-prefetch A tile,
// one barrier per chunk). Byte-identical to the R10/R11 WIN version.
// ---------------------------------------------------------------------------
__global__ __launch_bounds__(256)
void gemm1_kernel(const float* __restrict__ Wb) {
    __shared__ float As[2][32][64];   // [stage][k][m]
    __shared__ float Bs[2][32][64];   // [stage][k][n]

    int tid = threadIdx.x;
    int m0 = blockIdx.y * 64;
    int n0 = blockIdx.x * 64;
    int r  = n0 >> 8;
    int e0 = n0 & 255;
    const float* Bbase = Wb + (size_t)r * (D_ * D_) + e0;
    const float* A = g_pooled;

    int ty = tid >> 4, tx = tid & 15;          // 16x16 thread grid
    int ar = tid >> 3, ac = tid & 7;           // A loads
    int br = tid >> 4, bc = tid & 15;          // B loads

    unsigned bs_base = (unsigned)__cvta_generic_to_shared(&Bs[0][0][0]);

    float acc[4][4] = {};
    float4 pa[2];

    // ---- prologue: stage 0 ----
#pragma unroll
    for (int i = 0; i < 2; ++i)
        pa[i] = *(const float4*)(A + (size_t)(m0 + ar + i * 32) * D_ + ac * 4);
#pragma unroll
    for (int i = 0; i < 2; ++i) {
        unsigned dst = bs_base + (unsigned)(((br + i * 16) * 64 + bc * 4) * 4);
        const float* src = Bbase + (size_t)(br + i * 16) * D_ + bc * 4;
        asm volatile("cp.async.cg.shared.global [%0], [%1], 16;"
                     :: "r"(dst), "l"(src) : "memory");
    }
    asm volatile("cp.async.commit_group;" ::: "memory");
#pragma unroll
    for (int i = 0; i < 2; ++i) {
        int row = ar + i * 32;
        As[0][ac * 4 + 0][row] = pa[i].x;
        As[0][ac * 4 + 1][row] = pa[i].y;
        As[0][ac * 4 + 2][row] = pa[i].z;
        As[0][ac * 4 + 3][row] = pa[i].w;
    }
    asm volatile("cp.async.wait_group 0;" ::: "memory");
    __syncthreads();

    // ---- main loop: 8 chunks, one barrier each ----
#pragma unroll
    for (int it = 0; it < 8; ++it) {
        int c = it & 1;
        if (it < 7) {
            int k0 = (it + 1) * 32;
#pragma unroll
            for (int i = 0; i < 2; ++i)
                pa[i] = *(const float4*)(A + (size_t)(m0 + ar + i * 32) * D_ + k0 + ac * 4);
#pragma unroll
            for (int i = 0; i < 2; ++i) {
                unsigned dst = bs_base +
                    (unsigned)((((1 - c) * 32 + br + i * 16) * 64 + bc * 4) * 4);
                const float* src = Bbase + (size_t)(k0 + br + i * 16) * D_ + bc * 4;
                asm volatile("cp.async.cg.shared.global [%0], [%1], 16;"
                             :: "r"(dst), "l"(src) : "memory");
            }
            asm volatile("cp.async.commit_group;" ::: "memory");
        }

#pragma unroll
        for (int kk = 0; kk < 32; ++kk) {
            float4 a = *(float4*)&As[c][kk][ty * 4];
            float4 b = *(float4*)&Bs[c][kk][tx * 4];
            float av[4] = {a.x, a.y, a.z, a.w};
            float bv[4] = {b.x, b.y, b.z, b.w};
#pragma unroll
            for (int i = 0; i < 4; ++i)
#pragma unroll
                for (int j = 0; j < 4; ++j)
                    acc[i][j] += av[i] * bv[j];
        }

        if (it < 7) {
#pragma unroll
            for (int i = 0; i < 2; ++i) {
                int row = ar + i * 32;
                As[1 - c][ac * 4 + 0][row] = pa[i].x;
                As[1 - c][ac * 4 + 1][row] = pa[i].y;
                As[1 - c][ac * 4 + 2][row] = pa[i].z;
                As[1 - c][ac * 4 + 3][row] = pa[i].w;
            }
            asm volatile("cp.async.wait_group 0;" ::: "memory");
        }
        __syncthreads();
    }

#pragma unroll
    for (int i = 0; i < 4; ++i) {
        float4 v = make_float4(acc[i][0], acc[i][1], acc[i][2], acc[i][3]);
        *(float4*)(g_T1 + (size_t)(m0 + ty * 4 + i) * N1 + n0 + tx * 4) = v;
    }
}

// ---------------------------------------------------------------------------
// Kernel 3: GEMM2 + fused score epilogue. Byte-identical to the R11 WIN
// version (96 blocks, 64x64x256, 4x4 micro-tile, reg prefetch; G tile parked
// in smem reusing As; per-block pair gather writes out[b,p,r] directly).
// ---------------------------------------------------------------------------
__global__ __launch_bounds__(256)
void gemm2_kernel(const float* __restrict__ bias,
                  const int* __restrict__ ph,
                  const int* __restrict__ pt,
                  float* __restrict__ out) {
    int bid = blockIdx.x;                 // b*12 + r
    int b = bid / R_;
    int r = bid - b * R_;

    __shared__ float As[64][64];          // [e][s]; reused as G tile in epilogue
    __shared__ float Bs[64][64];          // [e][t]

    int tid = threadIdx.x;
    int ty = tid >> 4, tx = tid & 15;
    int lr = tid >> 2;                    // row 0..63
    int lc = tid & 3;                     // base float4 col group

    const float* Ab = g_T1 + (size_t)b * S_ * N1 + r * D_;   // row s: +s*N1
    const float* Bb = g_pooled + (size_t)b * S_ * D_;        // row t: +t*256

    float acc[4][4] = {};
    float4 va[4], vb[4];

    // prologue: e0 = 0
#pragma unroll
    for (int i = 0; i < 4; ++i) {
        int cg = lc + 4 * i;
        va[i] = *(const float4*)(Ab + (size_t)lr * N1 + cg * 4);
        vb[i] = *(const float4*)(Bb + lr * D_ + cg * 4);
    }

#pragma unroll
    for (int it = 0; it < 4; ++it) {
        // store current regs (transposed)
#pragma unroll
        for (int i = 0; i < 4; ++i) {
            int cg = lc + 4 * i;
            As[cg * 4 + 0][lr] = va[i].x;
            As[cg * 4 + 1][lr] = va[i].y;
            As[cg * 4 + 2][lr] = va[i].z;
            As[cg * 4 + 3][lr] = va[i].w;
            Bs[cg * 4 + 0][lr] = vb[i].x;
            Bs[cg * 4 + 1][lr] = vb[i].y;
            Bs[cg * 4 + 2][lr] = vb[i].z;
            Bs[cg * 4 + 3][lr] = vb[i].w;
        }
        __syncthreads();

        if (it < 3) {
            int e0 = (it + 1) * 64;
#pragma unroll
            for (int i = 0; i < 4; ++i) {
                int cg = lc + 4 * i;
                va[i] = *(const float4*)(Ab + (size_t)lr * N1 + e0 + cg * 4);
                vb[i] = *(const float4*)(Bb + lr * D_ + e0 + cg * 4);
            }
        }

#pragma unroll
        for (int kk = 0; kk < 64; ++kk) {
            float4 a = *(float4*)&As[kk][ty * 4];
            float4 bv = *(float4*)&Bs[kk][tx * 4];
            float av[4] = {a.x, a.y, a.z, a.w};
            float bw[4] = {bv.x, bv.y, bv.z, bv.w};
#pragma unroll
            for (int i = 0; i < 4; ++i)
#pragma unroll
                for (int j = 0; j < 4; ++j)
                    acc[i][j] += av[i] * bw[j];
        }
        __syncthreads();
    }

    // Park G tile in smem (As storage is free after the last barrier).
    float* sg = &As[0][0];
#pragma unroll
    for (int i = 0; i < 4; ++i) {
        *(float4*)&sg[(ty * 4 + i) * 64 + tx * 4] =
            make_float4(acc[i][0], acc[i][1], acc[i][2], acc[i][3]);
    }
    __syncthreads();

    // Fused pair-score gather: 1024 pairs / 256 threads = 4 each.
    float bv = bias[r];
    const float* Lb = g_L + (size_t)b * S_ * (2 * R_);
    const int* phb = ph + (b << 10);
    const int* ptb = pt + (b << 10);
#pragma unroll
    for (int i = 0; i < 4; ++i) {
        int p = tid + i * 256;
        int h = phb[p];
        int t = ptb[p];
        float sc = sg[h * 64 + t] + Lb[h * 24 + r] + Lb[t * 24 + 12 + r] + bv;
        out[(size_t)((b << 10) + p) * R_ + r] = 1.f / (1.f + __expf(-sc));
    }
}

// ---------------------------------------------------------------------------
// Launch.  Inputs in metadata order:
// 0 encoded f32 [8,512,256]   1 W_linear f32 [512,12]   2 b_linear f32 [12]
// 3 W_bilinear f32 [12,256,256]
// 4 span_starts i32 [8,64]    5 span_lens i32 [8,64]
// 6 pair_head i32 [8,1024]    7 pair_tail i32 [8,1024]
// Output f32 [8,1024,12].
// ---------------------------------------------------------------------------
extern "C" void kernel_launch(void* const* d_in, const int* in_sizes, int n_in,
                              void* d_out, int out_size) {
    const float* enc = (const float*)d_in[0];
    const float* Wl  = (const float*)d_in[1];
    const float* bl  = (const float*)d_in[2];
    const float* Wb  = (const float*)d_in[3];
    const int* sst   = (const int*)d_in[4];
    const int* sln   = (const int*)d_in[5];
    const int* ph    = (const int*)d_in[6];
    const int* pt    = (const int*)d_in[7];
    float* out = (float*)d_out;

    pool_kernel<<<B_ * S_, 256>>>(enc, Wl, sst, sln);
    gemm1_kernel<<<dim3(N1 / 64, (B_ * S_) / 64), 256>>>(Wb);
    gemm2_kernel<<<B_ * R_, 256>>>(bl, ph, pt, out);
}

// round 13
// speedup vs baseline: 1.7924x; 1.0778x over previous
#include <cuda_runtime.h>
#include <math.h>
#include <float.h>
#include <stdint.h>

// Problem constants
#define B_ 8
#define T_ 512
#define D_ 256
#define S_ 64
#define P_ 1024
#define R_ 12
#define N1 (R_ * D_)   // 3072: columns of GEMM1 output, n = r*256 + e

// Scratch (device globals — no allocation allowed)
__device__ float g_pooled[B_ * S_ * D_];        // fp32 pooled (for gemm2)
__device__ float g_pA_hi[B_ * S_ * D_];         // tf32-rounded pooled, hi part
__device__ float g_pA_lo[B_ * S_ * D_];         // tf32 lo residual
__device__ float g_L[B_ * S_ * 2 * R_];         // [bs][h*12+r]
__device__ float g_T1[B_ * S_ * N1];            // [bs][r*256+e]  6.3 MB
__device__ float g_wb_hi[R_ * D_ * D_];         // tf32 hi of W_bilinear (3 MB)
__device__ float g_wb_lo[R_ * D_ * D_];         // tf32 lo residual     (3 MB)

__device__ __forceinline__ float tf32r(float x) {
    uint32_t u;
    asm("cvt.rna.tf32.f32 %0, %1;" : "=r"(u) : "f"(x));
    return __uint_as_float(u);
}

// ---------------------------------------------------------------------------
// Kernel 1: ragged span max-pool + per-span linear terms (R12 form) + emit
// tf32 hi/lo split of pooled for the tensor-core GEMM1.
// ---------------------------------------------------------------------------
__global__ __launch_bounds__(256)
void pool_kernel(const float* __restrict__ enc,
                 const float* __restrict__ Wl,   // [2D, R] row-major
                 const int* __restrict__ starts,
                 const int* __restrict__ lens) {
    __shared__ float sp[D_];
    __shared__ float red[8 * 24];

    int bs  = blockIdx.x;          // b*64 + s
    int b   = bs >> 6;
    int tid = threadIdx.x;
    int warp = tid >> 5, lane = tid & 31;

    int st = starts[bs];
    int en = st + lens[bs] + 1;    // exclusive, >= st+1
    if (en > T_) en = T_;

    const float* p = enc + ((size_t)b * T_ + st) * D_ + tid;
    float m = -FLT_MAX;
    for (int t = st; t < en; ++t) { m = fmaxf(m, *p); p += D_; }
    g_pooled[bs * D_ + tid] = m;
    float hi = tf32r(m);
    g_pA_hi[bs * D_ + tid] = hi;
    g_pA_lo[bs * D_ + tid] = tf32r(m - hi);
    sp[tid] = m;
    __syncthreads();

    // lane o = h*12 + r (o < 24 active): warp w sweeps its 32 d-values.
    if (lane < 24) {
        int h = (lane >= 12);
        int r = lane - h * 12;
        const float* wp = Wl + h * (D_ * R_) + r;
        int d0 = warp * 32;
        float sum = 0.f;
#pragma unroll
        for (int dd = 0; dd < 32; ++dd) {
            int d = d0 + dd;
            sum += sp[d] * wp[d * R_];
        }
        red[warp * 24 + lane] = sum;
    }
    __syncthreads();

    if (tid < 24) {
        float s = 0.f;
#pragma unroll
        for (int wp8 = 0; wp8 < 8; ++wp8) s += red[wp8 * 24 + tid];
        g_L[bs * (2 * R_) + tid] = s;
    }
}

// ---------------------------------------------------------------------------
// Kernel 1b: split W_bilinear into tf32 hi/lo.  786432 floats.
// grid 256 x 256 threads, 3 float4 per thread.
// ---------------------------------------------------------------------------
__global__ __launch_bounds__(256)
void split_wb_kernel(const float* __restrict__ Wb) {
    int idx = blockIdx.x * 256 + threadIdx.x;     // 0..65535
    const float4* src = (const float4*)Wb;
    float4* dhi = (float4*)g_wb_hi;
    float4* dlo = (float4*)g_wb_lo;
#pragma unroll
    for (int i = 0; i < 3; ++i) {
        int j = idx + i * 65536;
        float4 v = src[j];
        float4 h, l;
        h.x = tf32r(v.x); l.x = tf32r(v.x - h.x);
        h.y = tf32r(v.y); l.y = tf32r(v.y - h.y);
        h.z = tf32r(v.z); l.z = tf32r(v.z - h.z);
        h.w = tf32r(v.w); l.w = tf32r(v.w - h.w);
        dhi[j] = h;
        dlo[j] = l;
    }
}

// ---------------------------------------------------------------------------
// Kernel 2: GEMM1 on tensor cores (3xTF32 mma.sync.m16n8k8).
// T1[(b,s),(r,e)] = sum_d pooled[(b,s),d] * Wb[r,d,e].
// BM=BN=64, BK=32, 256 threads = 8 warps in 2(m) x 4(n); warp tile 32x16 =
// 2x2 m16n8 fragments. acc += Ahi*Bhi + Ahi*Blo + Alo*Bhi (fp32 accumulate).
// Double-buffered dynamic smem (70 KB), all tiles via cp.async (R10 pipeline
// pattern: issue next stage, compute, wait, one barrier per chunk).
// Smem pitches: A 36 (bank-conflict-free frag reads, 144B rows 16B-aligned),
// B 68 (idem, 272B rows).
// ---------------------------------------------------------------------------
#define A_PITCH 36
#define B_PITCH 68
#define ASZ (64 * A_PITCH)          // floats
#define BSZ (32 * B_PITCH)
#define STAGE_F (2 * ASZ + 2 * BSZ) // 8960 floats = 35840 B
#define GEMM1_SMEM (2 * STAGE_F * 4)

#define MMA_TF32(C, A, Bv)                                                   \
    asm volatile(                                                            \
        "mma.sync.aligned.m16n8k8.row.col.f32.tf32.tf32.f32 "                \
        "{%0,%1,%2,%3}, {%4,%5,%6,%7}, {%8,%9}, {%0,%1,%2,%3};"              \
        : "+f"(C[0]), "+f"(C[1]), "+f"(C[2]), "+f"(C[3])                     \
        : "r"(A[0]), "r"(A[1]), "r"(A[2]), "r"(A[3]), "r"(Bv[0]), "r"(Bv[1]))

__global__ __launch_bounds__(256)
void gemm1_kernel() {
    extern __shared__ float smem[];

    int tid = threadIdx.x;
    int wid = tid >> 5, lane = tid & 31;
    int g = lane >> 2, c = lane & 3;
    int warp_m = wid >> 2;            // 0..1 -> m offset *32
    int warp_n = wid & 3;             // 0..3 -> n offset *16

    int m0 = blockIdx.y * 64;
    int n0 = blockIdx.x * 64;
    int r  = n0 >> 8;
    int e0 = n0 & 255;

    const float* pAhi = g_pA_hi;
    const float* pAlo = g_pA_lo;
    const float* wbh = g_wb_hi + (size_t)r * (D_ * D_) + e0;
    const float* wbl = g_wb_lo + (size_t)r * (D_ * D_) + e0;

    unsigned sbase = (unsigned)__cvta_generic_to_shared(smem);

    float acc[2][2][4] = {};

    // cp.async issue for one stage: 8 ops per thread.
    auto issue_stage = [&](int s, int k0) {
        unsigned st = sbase + (unsigned)(s * STAGE_F * 4);
#pragma unroll
        for (int i = 0; i < 2; ++i) {
            int op = tid + i * 256;          // 0..511
            int row = op >> 3, ch = op & 7;  // A: 64 rows x 8 chunks
            unsigned da = st + (unsigned)((row * A_PITCH + ch * 4) * 4);
            const float* sa = pAhi + (size_t)(m0 + row) * D_ + k0 + ch * 4;
            asm volatile("cp.async.cg.shared.global [%0], [%1], 16;"
                         :: "r"(da), "l"(sa) : "memory");
            unsigned da2 = da + (unsigned)(ASZ * 4);
            const float* sa2 = pAlo + (size_t)(m0 + row) * D_ + k0 + ch * 4;
            asm volatile("cp.async.cg.shared.global [%0], [%1], 16;"
                         :: "r"(da2), "l"(sa2) : "memory");
            int rk = op >> 4, chb = op & 15; // B: 32 k-rows x 16 chunks
            unsigned db = st + (unsigned)((2 * ASZ + rk * B_PITCH + chb * 4) * 4);
            const float* sb = wbh + (size_t)(k0 + rk) * D_ + chb * 4;
            asm volatile("cp.async.cg.shared.global [%0], [%1], 16;"
                         :: "r"(db), "l"(sb) : "memory");
            unsigned db2 = db + (unsigned)(BSZ * 4);
            const float* sb2 = wbl + (size_t)(k0 + rk) * D_ + chb * 4;
            asm volatile("cp.async.cg.shared.global [%0], [%1], 16;"
                         :: "r"(db2), "l"(sb2) : "memory");
        }
        asm volatile("cp.async.commit_group;" ::: "memory");
    };

    issue_stage(0, 0);
    asm volatile("cp.async.wait_group 0;" ::: "memory");
    __syncthreads();

#pragma unroll
    for (int it = 0; it < 8; ++it) {
        int s = it & 1;
        if (it < 7) issue_stage(1 - s, (it + 1) * 32);

        const float* Ah = smem + s * STAGE_F;
        const float* Al = Ah + ASZ;
        const float* Bh = smem + s * STAGE_F + 2 * ASZ;
        const float* Bl = Bh + BSZ;

#pragma unroll
        for (int k8 = 0; k8 < 4; ++k8) {
            int kc = k8 * 8 + c;
            uint32_t ah[2][4], al[2][4], bh[2][2], bl[2][2];
#pragma unroll
            for (int mi = 0; mi < 2; ++mi) {
                int rb = warp_m * 32 + mi * 16 + g;
                ah[mi][0] = __float_as_uint(Ah[rb * A_PITCH + kc]);
                ah[mi][1] = __float_as_uint(Ah[(rb + 8) * A_PITCH + kc]);
                ah[mi][2] = __float_as_uint(Ah[rb * A_PITCH + kc + 4]);
                ah[mi][3] = __float_as_uint(Ah[(rb + 8) * A_PITCH + kc + 4]);
                al[mi][0] = __float_as_uint(Al[rb * A_PITCH + kc]);
                al[mi][1] = __float_as_uint(Al[(rb + 8) * A_PITCH + kc]);
                al[mi][2] = __float_as_uint(Al[rb * A_PITCH + kc + 4]);
                al[mi][3] = __float_as_uint(Al[(rb + 8) * A_PITCH + kc + 4]);
            }
#pragma unroll
            for (int ni = 0; ni < 2; ++ni) {
                int nb = warp_n * 16 + ni * 8 + g;
                bh[ni][0] = __float_as_uint(Bh[kc * B_PITCH + nb]);
                bh[ni][1] = __float_as_uint(Bh[(kc + 4) * B_PITCH + nb]);
                bl[ni][0] = __float_as_uint(Bl[kc * B_PITCH + nb]);
                bl[ni][1] = __float_as_uint(Bl[(kc + 4) * B_PITCH + nb]);
            }
#pragma unroll
            for (int mi = 0; mi < 2; ++mi)
#pragma unroll
                for (int ni = 0; ni < 2; ++ni) {
                    MMA_TF32(acc[mi][ni], ah[mi], bh[ni]);
                    MMA_TF32(acc[mi][ni], ah[mi], bl[ni]);
                    MMA_TF32(acc[mi][ni], al[mi], bh[ni]);
                }
        }

        if (it < 7) asm volatile("cp.async.wait_group 0;" ::: "memory");
        __syncthreads();
    }

    // Epilogue: C frag (mi,ni): rows warp_m*32+mi*16+g (+8), cols 2c (+1).
#pragma unroll
    for (int mi = 0; mi < 2; ++mi)
#pragma unroll
        for (int ni = 0; ni < 2; ++ni) {
            int row = m0 + warp_m * 32 + mi * 16 + g;
            int col = n0 + warp_n * 16 + ni * 8 + 2 * c;
            *(float2*)&g_T1[(size_t)row * N1 + col] =
                make_float2(acc[mi][ni][0], acc[mi][ni][1]);
            *(float2*)&g_T1[(size_t)(row + 8) * N1 + col] =
                make_float2(acc[mi][ni][2], acc[mi][ni][3]);
        }
}

// ---------------------------------------------------------------------------
// Kernel 3: GEMM2 + fused score epilogue. Byte-identical to the R11/R12 WIN
// version (96 blocks, 64x64x256, 4x4 micro-tile, reg prefetch; G tile parked
// in smem reusing As; per-block pair gather writes out[b,p,r] directly).
// ---------------------------------------------------------------------------
__global__ __launch_bounds__(256)
void gemm2_kernel(const float* __restrict__ bias,
                  const int* __restrict__ ph,
                  const int* __restrict__ pt,
                  float* __restrict__ out) {
    int bid = blockIdx.x;                 // b*12 + r
    int b = bid / R_;
    int r = bid - b * R_;

    __shared__ float As[64][64];          // [e][s]; reused as G tile in epilogue
    __shared__ float Bs[64][64];          // [e][t]

    int tid = threadIdx.x;
    int ty = tid >> 4, tx = tid & 15;
    int lr = tid >> 2;                    // row 0..63
    int lc = tid & 3;                     // base float4 col group

    const float* Ab = g_T1 + (size_t)b * S_ * N1 + r * D_;   // row s: +s*N1
    const float* Bb = g_pooled + (size_t)b * S_ * D_;        // row t: +t*256

    float acc[4][4] = {};
    float4 va[4], vb[4];

    // prologue: e0 = 0
#pragma unroll
    for (int i = 0; i < 4; ++i) {
        int cg = lc + 4 * i;
        va[i] = *(const float4*)(Ab + (size_t)lr * N1 + cg * 4);
        vb[i] = *(const float4*)(Bb + lr * D_ + cg * 4);
    }

#pragma unroll
    for (int it = 0; it < 4; ++it) {
#pragma unroll
        for (int i = 0; i < 4; ++i) {
            int cg = lc + 4 * i;
            As[cg * 4 + 0][lr] = va[i].x;
            As[cg * 4 + 1][lr] = va[i].y;
            As[cg * 4 + 2][lr] = va[i].z;
            As[cg * 4 + 3][lr] = va[i].w;
            Bs[cg * 4 + 0][lr] = vb[i].x;
            Bs[cg * 4 + 1][lr] = vb[i].y;
            Bs[cg * 4 + 2][lr] = vb[i].z;
            Bs[cg * 4 + 3][lr] = vb[i].w;
        }
        __syncthreads();

        if (it < 3) {
            int e0 = (it + 1) * 64;
#pragma unroll
            for (int i = 0; i < 4; ++i) {
                int cg = lc + 4 * i;
                va[i] = *(const float4*)(Ab + (size_t)lr * N1 + e0 + cg * 4);
                vb[i] = *(const float4*)(Bb + lr * D_ + e0 + cg * 4);
            }
        }

#pragma unroll
        for (int kk = 0; kk < 64; ++kk) {
            float4 a = *(float4*)&As[kk][ty * 4];
            float4 bv = *(float4*)&Bs[kk][tx * 4];
            float av[4] = {a.x, a.y, a.z, a.w};
            float bw[4] = {bv.x, bv.y, bv.z, bv.w};
#pragma unroll
            for (int i = 0; i < 4; ++i)
#pragma unroll
                for (int j = 0; j < 4; ++j)
                    acc[i][j] += av[i] * bw[j];
        }
        __syncthreads();
    }

    // Park G tile in smem (As storage is free after the last barrier).
    float* sg = &As[0][0];
#pragma unroll
    for (int i = 0; i < 4; ++i) {
        *(float4*)&sg[(ty * 4 + i) * 64 + tx * 4] =
            make_float4(acc[i][0], acc[i][1], acc[i][2], acc[i][3]);
    }
    __syncthreads();

    // Fused pair-score gather: 1024 pairs / 256 threads = 4 each.
    float bv = bias[r];
    const float* Lb = g_L + (size_t)b * S_ * (2 * R_);
    const int* phb = ph + (b << 10);
    const int* ptb = pt + (b << 10);
#pragma unroll
    for (int i = 0; i < 4; ++i) {
        int p = tid + i * 256;
        int h = phb[p];
        int t = ptb[p];
        float sc = sg[h * 64 + t] + Lb[h * 24 + r] + Lb[t * 24 + 12 + r] + bv;
        out[(size_t)((b << 10) + p) * R_ + r] = 1.f / (1.f + __expf(-sc));
    }
}

// ---------------------------------------------------------------------------
// Launch.  Inputs in metadata order:
// 0 encoded f32 [8,512,256]   1 W_linear f32 [512,12]   2 b_linear f32 [12]
// 3 W_bilinear f32 [12,256,256]
// 4 span_starts i32 [8,64]    5 span_lens i32 [8,64]
// 6 pair_head i32 [8,1024]    7 pair_tail i32 [8,1024]
// Output f32 [8,1024,12].
// ---------------------------------------------------------------------------
extern "C" void kernel_launch(void* const* d_in, const int* in_sizes, int n_in,
                              void* d_out, int out_size) {
    const float* enc = (const float*)d_in[0];
    const float* Wl  = (const float*)d_in[1];
    const float* bl  = (const float*)d_in[2];
    const float* Wb  = (const float*)d_in[3];
    const int* sst   = (const int*)d_in[4];
    const int* sln   = (const int*)d_in[5];
    const int* ph    = (const int*)d_in[6];
    const int* pt    = (const int*)d_in[7];
    float* out = (float*)d_out;

    cudaFuncSetAttribute(gemm1_kernel,
                         cudaFuncAttributeMaxDynamicSharedMemorySize,
                         GEMM1_SMEM);

    pool_kernel<<<B_ * S_, 256>>>(enc, Wl, sst, sln);
    split_wb_kernel<<<256, 256>>>(Wb);
    gemm1_kernel<<<dim3(N1 / 64, (B_ * S_) / 64), 256, GEMM1_SMEM>>>();
    gemm2_kernel<<<B_ * R_, 256>>>(bl, ph, pt, out);
}

// round 14
// speedup vs baseline: 1.8978x; 1.0588x over previous
#include <cuda_runtime.h>
#include <math.h>
#include <float.h>
#include <stdint.h>

// Problem constants
#define B_ 8
#define T_ 512
#define D_ 256
#define S_ 64
#define P_ 1024
#define R_ 12
#define N1 (R_ * D_)   // 3072: columns of GEMM1 output, n = r*256 + e

// Scratch (device globals — no allocation allowed)
__device__ float g_pA_hi[B_ * S_ * D_];         // tf32-rounded pooled, hi part
__device__ float g_pA_lo[B_ * S_ * D_];         // tf32 lo residual
__device__ float g_L[B_ * S_ * 2 * R_];         // [bs][h*12+r]
__device__ float g_T1hi[B_ * S_ * N1];          // tf32 hi of T1 (6.3 MB)
__device__ float g_T1lo[B_ * S_ * N1];          // tf32 lo residual (6.3 MB)
__device__ float g_wb_hi[R_ * D_ * D_];         // tf32 hi of W_bilinear (3 MB)
__device__ float g_wb_lo[R_ * D_ * D_];         // tf32 lo residual     (3 MB)

__device__ __forceinline__ float tf32r(float x) {
    uint32_t u;
    asm("cvt.rna.tf32.f32 %0, %1;" : "=r"(u) : "f"(x));
    return __uint_as_float(u);
}

#define MMA_TF32(C, A, Bv)                                                   \
    asm volatile(                                                            \
        "mma.sync.aligned.m16n8k8.row.col.f32.tf32.tf32.f32 "                \
        "{%0,%1,%2,%3}, {%4,%5,%6,%7}, {%8,%9}, {%0,%1,%2,%3};"              \
        : "+f"(C[0]), "+f"(C[1]), "+f"(C[2]), "+f"(C[3])                     \
        : "r"(A[0]), "r"(A[1]), "r"(A[2]), "r"(A[3]), "r"(Bv[0]), "r"(Bv[1]))

// ---------------------------------------------------------------------------
// Kernel 1: ragged span max-pool + per-span linear terms (R12 form), emitting
// tf32 hi/lo split of pooled (consumed by BOTH tensor-core GEMMs).
// ---------------------------------------------------------------------------
__global__ __launch_bounds__(256)
void pool_kernel(const float* __restrict__ enc,
                 const float* __restrict__ Wl,   // [2D, R] row-major
                 const int* __restrict__ starts,
                 const int* __restrict__ lens) {
    __shared__ float sp[D_];
    __shared__ float red[8 * 24];

    int bs  = blockIdx.x;          // b*64 + s
    int b   = bs >> 6;
    int tid = threadIdx.x;
    int warp = tid >> 5, lane = tid & 31;

    int st = starts[bs];
    int en = st + lens[bs] + 1;    // exclusive, >= st+1
    if (en > T_) en = T_;

    const float* p = enc + ((size_t)b * T_ + st) * D_ + tid;
    float m = -FLT_MAX;
    for (int t = st; t < en; ++t) { m = fmaxf(m, *p); p += D_; }
    float hi = tf32r(m);
    g_pA_hi[bs * D_ + tid] = hi;
    g_pA_lo[bs * D_ + tid] = tf32r(m - hi);
    sp[tid] = m;
    __syncthreads();

    // lane o = h*12 + r (o < 24 active): warp w sweeps its 32 d-values.
    if (lane < 24) {
        int h = (lane >= 12);
        int r = lane - h * 12;
        const float* wp = Wl + h * (D_ * R_) + r;
        int d0 = warp * 32;
        float sum = 0.f;
#pragma unroll
        for (int dd = 0; dd < 32; ++dd) {
            int d = d0 + dd;
            sum += sp[d] * wp[d * R_];
        }
        red[warp * 24 + lane] = sum;
    }
    __syncthreads();

    if (tid < 24) {
        float s = 0.f;
#pragma unroll
        for (int wp8 = 0; wp8 < 8; ++wp8) s += red[wp8 * 24 + tid];
        g_L[bs * (2 * R_) + tid] = s;
    }
}

// ---------------------------------------------------------------------------
// Kernel 1b: split W_bilinear into tf32 hi/lo. (proven R13 form)
// ---------------------------------------------------------------------------
__global__ __launch_bounds__(256)
void split_wb_kernel(const float* __restrict__ Wb) {
    int idx = blockIdx.x * 256 + threadIdx.x;     // 0..65535
    const float4* src = (const float4*)Wb;
    float4* dhi = (float4*)g_wb_hi;
    float4* dlo = (float4*)g_wb_lo;
#pragma unroll
    for (int i = 0; i < 3; ++i) {
        int j = idx + i * 65536;
        float4 v = src[j];
        float4 h, l;
        h.x = tf32r(v.x); l.x = tf32r(v.x - h.x);
        h.y = tf32r(v.y); l.y = tf32r(v.y - h.y);
        h.z = tf32r(v.z); l.z = tf32r(v.z - h.z);
        h.w = tf32r(v.w); l.w = tf32r(v.w - h.w);
        dhi[j] = h;
        dlo[j] = l;
    }
}

// ---------------------------------------------------------------------------
// Kernel 2: GEMM1 on tensor cores (3xTF32), proven R13 form; epilogue now
// writes tf32 hi/lo split of T1 for the tensor-core GEMM2.
// ---------------------------------------------------------------------------
#define A_PITCH 36
#define B_PITCH 68
#define ASZ (64 * A_PITCH)          // floats
#define BSZ (32 * B_PITCH)
#define STAGE_F (2 * ASZ + 2 * BSZ) // 8960 floats = 35840 B
#define GEMM1_SMEM (2 * STAGE_F * 4)

__global__ __launch_bounds__(256)
void gemm1_kernel() {
    extern __shared__ float smem[];

    int tid = threadIdx.x;
    int wid = tid >> 5, lane = tid & 31;
    int g = lane >> 2, c = lane & 3;
    int warp_m = wid >> 2;            // 0..1 -> m offset *32
    int warp_n = wid & 3;             // 0..3 -> n offset *16

    int m0 = blockIdx.y * 64;
    int n0 = blockIdx.x * 64;
    int r  = n0 >> 8;
    int e0 = n0 & 255;

    const float* pAhi = g_pA_hi;
    const float* pAlo = g_pA_lo;
    const float* wbh = g_wb_hi + (size_t)r * (D_ * D_) + e0;
    const float* wbl = g_wb_lo + (size_t)r * (D_ * D_) + e0;

    unsigned sbase = (unsigned)__cvta_generic_to_shared(smem);

    float acc[2][2][4] = {};

    auto issue_stage = [&](int s, int k0) {
        unsigned st = sbase + (unsigned)(s * STAGE_F * 4);
#pragma unroll
        for (int i = 0; i < 2; ++i) {
            int op = tid + i * 256;          // 0..511
            int row = op >> 3, ch = op & 7;  // A: 64 rows x 8 chunks
            unsigned da = st + (unsigned)((row * A_PITCH + ch * 4) * 4);
            const float* sa = pAhi + (size_t)(m0 + row) * D_ + k0 + ch * 4;
            asm volatile("cp.async.cg.shared.global [%0], [%1], 16;"
                         :: "r"(da), "l"(sa) : "memory");
            unsigned da2 = da + (unsigned)(ASZ * 4);
            const float* sa2 = pAlo + (size_t)(m0 + row) * D_ + k0 + ch * 4;
            asm volatile("cp.async.cg.shared.global [%0], [%1], 16;"
                         :: "r"(da2), "l"(sa2) : "memory");
            int rk = op >> 4, chb = op & 15; // B: 32 k-rows x 16 chunks
            unsigned db = st + (unsigned)((2 * ASZ + rk * B_PITCH + chb * 4) * 4);
            const float* sb = wbh + (size_t)(k0 + rk) * D_ + chb * 4;
            asm volatile("cp.async.cg.shared.global [%0], [%1], 16;"
                         :: "r"(db), "l"(sb) : "memory");
            unsigned db2 = db + (unsigned)(BSZ * 4);
            const float* sb2 = wbl + (size_t)(k0 + rk) * D_ + chb * 4;
            asm volatile("cp.async.cg.shared.global [%0], [%1], 16;"
                         :: "r"(db2), "l"(sb2) : "memory");
        }
        asm volatile("cp.async.commit_group;" ::: "memory");
    };

    issue_stage(0, 0);
    asm volatile("cp.async.wait_group 0;" ::: "memory");
    __syncthreads();

#pragma unroll
    for (int it = 0; it < 8; ++it) {
        int s = it & 1;
        if (it < 7) issue_stage(1 - s, (it + 1) * 32);

        const float* Ah = smem + s * STAGE_F;
        const float* Al = Ah + ASZ;
        const float* Bh = smem + s * STAGE_F + 2 * ASZ;
        const float* Bl = Bh + BSZ;

#pragma unroll
        for (int k8 = 0; k8 < 4; ++k8) {
            int kc = k8 * 8 + c;
            uint32_t ah[2][4], al[2][4], bh[2][2], bl[2][2];
#pragma unroll
            for (int mi = 0; mi < 2; ++mi) {
                int rb = warp_m * 32 + mi * 16 + g;
                ah[mi][0] = __float_as_uint(Ah[rb * A_PITCH + kc]);
                ah[mi][1] = __float_as_uint(Ah[(rb + 8) * A_PITCH + kc]);
                ah[mi][2] = __float_as_uint(Ah[rb * A_PITCH + kc + 4]);
                ah[mi][3] = __float_as_uint(Ah[(rb + 8) * A_PITCH + kc + 4]);
                al[mi][0] = __float_as_uint(Al[rb * A_PITCH + kc]);
                al[mi][1] = __float_as_uint(Al[(rb + 8) * A_PITCH + kc]);
                al[mi][2] = __float_as_uint(Al[rb * A_PITCH + kc + 4]);
                al[mi][3] = __float_as_uint(Al[(rb + 8) * A_PITCH + kc + 4]);
            }
#pragma unroll
            for (int ni = 0; ni < 2; ++ni) {
                int nb = warp_n * 16 + ni * 8 + g;
                bh[ni][0] = __float_as_uint(Bh[kc * B_PITCH + nb]);
                bh[ni][1] = __float_as_uint(Bh[(kc + 4) * B_PITCH + nb]);
                bl[ni][0] = __float_as_uint(Bl[kc * B_PITCH + nb]);
                bl[ni][1] = __float_as_uint(Bl[(kc + 4) * B_PITCH + nb]);
            }
#pragma unroll
            for (int mi = 0; mi < 2; ++mi)
#pragma unroll
                for (int ni = 0; ni < 2; ++ni) {
                    MMA_TF32(acc[mi][ni], ah[mi], bh[ni]);
                    MMA_TF32(acc[mi][ni], ah[mi], bl[ni]);
                    MMA_TF32(acc[mi][ni], al[mi], bh[ni]);
                }
        }

        if (it < 7) asm volatile("cp.async.wait_group 0;" ::: "memory");
        __syncthreads();
    }

    // Epilogue: split T1 into tf32 hi/lo and store both.
#pragma unroll
    for (int mi = 0; mi < 2; ++mi)
#pragma unroll
        for (int ni = 0; ni < 2; ++ni) {
            int row = m0 + warp_m * 32 + mi * 16 + g;
            int col = n0 + warp_n * 16 + ni * 8 + 2 * c;
            float v0 = acc[mi][ni][0], v1 = acc[mi][ni][1];
            float v2 = acc[mi][ni][2], v3 = acc[mi][ni][3];
            float h0 = tf32r(v0), h1 = tf32r(v1), h2 = tf32r(v2), h3 = tf32r(v3);
            *(float2*)&g_T1hi[(size_t)row * N1 + col] = make_float2(h0, h1);
            *(float2*)&g_T1lo[(size_t)row * N1 + col] =
                make_float2(tf32r(v0 - h0), tf32r(v1 - h1));
            *(float2*)&g_T1hi[(size_t)(row + 8) * N1 + col] = make_float2(h2, h3);
            *(float2*)&g_T1lo[(size_t)(row + 8) * N1 + col] =
                make_float2(tf32r(v2 - h2), tf32r(v3 - h3));
        }
}

// ---------------------------------------------------------------------------
// Kernel 3: GEMM2 on tensor cores (3xTF32) + fused score epilogue.
// One block per (b,r): G[s,t] = sum_e T1[b,s,r*256+e] * pooled[b,t,e].
// Same 64x64x256 tile and pipeline as gemm1. A tile = T1 hi/lo [s][e]
// (row-major, direct cp.async). B tile = pooled hi/lo [t][e] — already
// k-contiguous per n ("col" operand), direct cp.async, fragment reads
// Bs[t*36 + e] are bank-conflict-free. Epilogue: G frags -> smem tile ->
// per-block pair gather writes out[b,p,r] (proven R11 fusion).
// ---------------------------------------------------------------------------
#define G2_PITCH 36
#define G2_TILE (64 * G2_PITCH)       // 2304 floats
#define G2_STAGE (4 * G2_TILE)        // 9216 floats = 36864 B
#define GEMM2_SMEM (2 * G2_STAGE * 4) // 73728 B

__global__ __launch_bounds__(256)
void gemm2_kernel(const float* __restrict__ bias,
                  const int* __restrict__ ph,
                  const int* __restrict__ pt,
                  float* __restrict__ out) {
    extern __shared__ float smem[];

    int bid = blockIdx.x;                 // b*12 + r
    int b = bid / R_;
    int r = bid - b * R_;

    int tid = threadIdx.x;
    int wid = tid >> 5, lane = tid & 31;
    int g = lane >> 2, c = lane & 3;
    int warp_m = wid >> 2;            // 0..1 -> s offset *32
    int warp_n = wid & 3;             // 0..3 -> t offset *16

    const float* Ahg = g_T1hi + (size_t)b * S_ * N1 + r * D_;   // row s: +s*N1
    const float* Alg = g_T1lo + (size_t)b * S_ * N1 + r * D_;
    const float* Bhg = g_pA_hi + (size_t)b * S_ * D_;           // row t: +t*256
    const float* Blg = g_pA_lo + (size_t)b * S_ * D_;

    unsigned sbase = (unsigned)__cvta_generic_to_shared(smem);

    float acc[2][2][4] = {};

    // 4 tiles x 64 rows x 8 16B-chunks = 2048 cp.async / 256 threads.
    auto issue_stage = [&](int s, int k0) {
        unsigned st = sbase + (unsigned)(s * G2_STAGE * 4);
#pragma unroll
        for (int i = 0; i < 2; ++i) {
            int op = tid + i * 256;          // 0..511
            int row = op >> 3, ch = op & 7;
            unsigned d0 = st + (unsigned)((row * G2_PITCH + ch * 4) * 4);
            const float* s0 = Ahg + (size_t)row * N1 + k0 + ch * 4;
            asm volatile("cp.async.cg.shared.global [%0], [%1], 16;"
                         :: "r"(d0), "l"(s0) : "memory");
            unsigned d1 = d0 + (unsigned)(G2_TILE * 4);
            const float* s1 = Alg + (size_t)row * N1 + k0 + ch * 4;
            asm volatile("cp.async.cg.shared.global [%0], [%1], 16;"
                         :: "r"(d1), "l"(s1) : "memory");
            unsigned d2 = d1 + (unsigned)(G2_TILE * 4);
            const float* s2 = Bhg + (size_t)row * D_ + k0 + ch * 4;
            asm volatile("cp.async.cg.shared.global [%0], [%1], 16;"
                         :: "r"(d2), "l"(s2) : "memory");
            unsigned d3 = d2 + (unsigned)(G2_TILE * 4);
            const float* s3 = Blg + (size_t)row * D_ + k0 + ch * 4;
            asm volatile("cp.async.cg.shared.global [%0], [%1], 16;"
                         :: "r"(d3), "l"(s3) : "memory");
        }
        asm volatile("cp.async.commit_group;" ::: "memory");
    };

    issue_stage(0, 0);
    asm volatile("cp.async.wait_group 0;" ::: "memory");
    __syncthreads();

#pragma unroll
    for (int it = 0; it < 8; ++it) {
        int s = it & 1;
        if (it < 7) issue_stage(1 - s, (it + 1) * 32);

        const float* Ah = smem + s * G2_STAGE;
        const float* Al = Ah + G2_TILE;
        const float* Bh = Al + G2_TILE;
        const float* Bl = Bh + G2_TILE;

#pragma unroll
        for (int k8 = 0; k8 < 4; ++k8) {
            int kc = k8 * 8 + c;
            uint32_t ah[2][4], al[2][4], bh[2][2], bl[2][2];
#pragma unroll
            for (int mi = 0; mi < 2; ++mi) {
                int rb = warp_m * 32 + mi * 16 + g;
                ah[mi][0] = __float_as_uint(Ah[rb * G2_PITCH + kc]);
                ah[mi][1] = __float_as_uint(Ah[(rb + 8) * G2_PITCH + kc]);
                ah[mi][2] = __float_as_uint(Ah[rb * G2_PITCH + kc + 4]);
                ah[mi][3] = __float_as_uint(Ah[(rb + 8) * G2_PITCH + kc + 4]);
                al[mi][0] = __float_as_uint(Al[rb * G2_PITCH + kc]);
                al[mi][1] = __float_as_uint(Al[(rb + 8) * G2_PITCH + kc]);
                al[mi][2] = __float_as_uint(Al[rb * G2_PITCH + kc + 4]);
                al[mi][3] = __float_as_uint(Al[(rb + 8) * G2_PITCH + kc + 4]);
            }
#pragma unroll
            for (int ni = 0; ni < 2; ++ni) {
                int nb = warp_n * 16 + ni * 8 + g;
                bh[ni][0] = __float_as_uint(Bh[nb * G2_PITCH + kc]);
                bh[ni][1] = __float_as_uint(Bh[nb * G2_PITCH + kc + 4]);
                bl[ni][0] = __float_as_uint(Bl[nb * G2_PITCH + kc]);
                bl[ni][1] = __float_as_uint(Bl[nb * G2_PITCH + kc + 4]);
            }
#pragma unroll
            for (int mi = 0; mi < 2; ++mi)
#pragma unroll
                for (int ni = 0; ni < 2; ++ni) {
                    MMA_TF32(acc[mi][ni], ah[mi], bh[ni]);
                    MMA_TF32(acc[mi][ni], ah[mi], bl[ni]);
                    MMA_TF32(acc[mi][ni], al[mi], bh[ni]);
                }
        }

        if (it < 7) asm volatile("cp.async.wait_group 0;" ::: "memory");
        __syncthreads();
    }

    // Park G tile in smem (pipeline stages are dead now), then pair gather.
    float* sg = smem;                 // 64x64 = 16 KB
#pragma unroll
    for (int mi = 0; mi < 2; ++mi)
#pragma unroll
        for (int ni = 0; ni < 2; ++ni) {
            int row = warp_m * 32 + mi * 16 + g;
            int col = warp_n * 16 + ni * 8 + 2 * c;
            sg[row * 64 + col]       = acc[mi][ni][0];
            sg[row * 64 + col + 1]   = acc[mi][ni][1];
            sg[(row + 8) * 64 + col]     = acc[mi][ni][2];
            sg[(row + 8) * 64 + col + 1] = acc[mi][ni][3];
        }
    __syncthreads();

    // Fused pair-score gather: 1024 pairs / 256 threads = 4 each.
    float bv = bias[r];
    const float* Lb = g_L + (size_t)b * S_ * (2 * R_);
    const int* phb = ph + (b << 10);
    const int* ptb = pt + (b << 10);
#pragma unroll
    for (int i = 0; i < 4; ++i) {
        int p = tid + i * 256;
        int h = phb[p];
        int t = ptb[p];
        float sc = sg[h * 64 + t] + Lb[h * 24 + r] + Lb[t * 24 + 12 + r] + bv;
        out[(size_t)((b << 10) + p) * R_ + r] = 1.f / (1.f + __expf(-sc));
    }
}

// ---------------------------------------------------------------------------
// Launch.  Inputs in metadata order:
// 0 encoded f32 [8,512,256]   1 W_linear f32 [512,12]   2 b_linear f32 [12]
// 3 W_bilinear f32 [12,256,256]
// 4 span_starts i32 [8,64]    5 span_lens i32 [8,64]
// 6 pair_head i32 [8,1024]    7 pair_tail i32 [8,1024]
// Output f32 [8,1024,12].
// ---------------------------------------------------------------------------
extern "C" void kernel_launch(void* const* d_in, const int* in_sizes, int n_in,
                              void* d_out, int out_size) {
    const float* enc = (const float*)d_in[0];
    const float* Wl  = (const float*)d_in[1];
    const float* bl  = (const float*)d_in[2];
    const float* Wb  = (const float*)d_in[3];
    const int* sst   = (const int*)d_in[4];
    const int* sln   = (const int*)d_in[5];
    const int* ph    = (const int*)d_in[6];
    const int* pt    = (const int*)d_in[7];
    float* out = (float*)d_out;

    cudaFuncSetAttribute(gemm1_kernel,
                         cudaFuncAttributeMaxDynamicSharedMemorySize,
                         GEMM1_SMEM);
    cudaFuncSetAttribute(gemm2_kernel,
                         cudaFuncAttributeMaxDynamicSharedMemorySize,
                         GEMM2_SMEM);

    pool_kernel<<<B_ * S_, 256>>>(enc, Wl, sst, sln);
    split_wb_kernel<<<256, 256>>>(Wb);
    gemm1_kernel<<<dim3(N1 / 64, (B_ * S_) / 64), 256, GEMM1_SMEM>>>();
    gemm2_kernel<<<B_ * R_, 256, GEMM2_SMEM>>>(bl, ph, pt, out);
}

// round 15
// speedup vs baseline: 1.8992x; 1.0007x over previous
#include <cuda_runtime.h>
#include <math.h>
#include <float.h>
#include <stdint.h>

// Problem constants
#define B_ 8
#define T_ 512
#define D_ 256
#define S_ 64
#define P_ 1024
#define R_ 12
#define N1 (R_ * D_)   // 3072: columns of GEMM1 output, n = r*256 + e

// Scratch (device globals — no allocation allowed)
__device__ float g_pA_hi[B_ * S_ * D_];         // tf32-rounded pooled, hi part
__device__ float g_pA_lo[B_ * S_ * D_];         // tf32 lo residual
__device__ float g_L[B_ * S_ * 2 * R_];         // [bs][h*12+r]
__device__ float g_T1hi[B_ * S_ * N1];          // tf32 hi of T1 (6.3 MB)
__device__ float g_T1lo[B_ * S_ * N1];          // tf32 lo residual (6.3 MB)
__device__ float g_wb_hi[R_ * D_ * D_];         // tf32 hi of W_bilinear (3 MB)
__device__ float g_wb_lo[R_ * D_ * D_];         // tf32 lo residual     (3 MB)

__device__ __forceinline__ float tf32r(float x) {
    uint32_t u;
    asm("cvt.rna.tf32.f32 %0, %1;" : "=r"(u) : "f"(x));
    return __uint_as_float(u);
}

#define MMA_TF32(C, A, Bv)                                                   \
    asm volatile(                                                            \
        "mma.sync.aligned.m16n8k8.row.col.f32.tf32.tf32.f32 "                \
        "{%0,%1,%2,%3}, {%4,%5,%6,%7}, {%8,%9}, {%0,%1,%2,%3};"              \
        : "+f"(C[0]), "+f"(C[1]), "+f"(C[2]), "+f"(C[3])                     \
        : "r"(A[0]), "r"(A[1]), "r"(A[2]), "r"(A[3]), "r"(Bv[0]), "r"(Bv[1]))

// ---------------------------------------------------------------------------
// Kernel 1: ragged span max-pool + per-span linear terms (proven form),
// emitting tf32 hi/lo split of pooled (consumed by BOTH tensor-core GEMMs).
// ---------------------------------------------------------------------------
__global__ __launch_bounds__(256)
void pool_kernel(const float* __restrict__ enc,
                 const float* __restrict__ Wl,   // [2D, R] row-major
                 const int* __restrict__ starts,
                 const int* __restrict__ lens) {
    __shared__ float sp[D_];
    __shared__ float red[8 * 24];

    int bs  = blockIdx.x;          // b*64 + s
    int b   = bs >> 6;
    int tid = threadIdx.x;
    int warp = tid >> 5, lane = tid & 31;

    int st = starts[bs];
    int en = st + lens[bs] + 1;    // exclusive, >= st+1
    if (en > T_) en = T_;

    const float* p = enc + ((size_t)b * T_ + st) * D_ + tid;
    float m = -FLT_MAX;
    for (int t = st; t < en; ++t) { m = fmaxf(m, *p); p += D_; }
    float hi = tf32r(m);
    g_pA_hi[bs * D_ + tid] = hi;
    g_pA_lo[bs * D_ + tid] = tf32r(m - hi);
    sp[tid] = m;
    __syncthreads();

    // lane o = h*12 + r (o < 24 active): warp w sweeps its 32 d-values.
    if (lane < 24) {
        int h = (lane >= 12);
        int r = lane - h * 12;
        const float* wp = Wl + h * (D_ * R_) + r;
        int d0 = warp * 32;
        float sum = 0.f;
#pragma unroll
        for (int dd = 0; dd < 32; ++dd) {
            int d = d0 + dd;
            sum += sp[d] * wp[d * R_];
        }
        red[warp * 24 + lane] = sum;
    }
    __syncthreads();

    if (tid < 24) {
        float s = 0.f;
#pragma unroll
        for (int wp8 = 0; wp8 < 8; ++wp8) s += red[wp8 * 24 + tid];
        g_L[bs * (2 * R_) + tid] = s;
    }
}

// ---------------------------------------------------------------------------
// Kernel 1b: split W_bilinear into tf32 hi/lo. (proven R13 form)
// ---------------------------------------------------------------------------
__global__ __launch_bounds__(256)
void split_wb_kernel(const float* __restrict__ Wb) {
    int idx = blockIdx.x * 256 + threadIdx.x;     // 0..65535
    const float4* src = (const float4*)Wb;
    float4* dhi = (float4*)g_wb_hi;
    float4* dlo = (float4*)g_wb_lo;
#pragma unroll
    for (int i = 0; i < 3; ++i) {
        int j = idx + i * 65536;
        float4 v = src[j];
        float4 h, l;
        h.x = tf32r(v.x); l.x = tf32r(v.x - h.x);
        h.y = tf32r(v.y); l.y = tf32r(v.y - h.y);
        h.z = tf32r(v.z); l.z = tf32r(v.z - h.z);
        h.w = tf32r(v.w); l.w = tf32r(v.w - h.w);
        dhi[j] = h;
        dlo[j] = l;
    }
}

// ---------------------------------------------------------------------------
// Kernel 2: GEMM1 on tensor cores (3xTF32), byte-identical to R14 WIN form.
// ---------------------------------------------------------------------------
#define A_PITCH 36
#define B_PITCH 68
#define ASZ (64 * A_PITCH)          // floats
#define BSZ (32 * B_PITCH)
#define STAGE_F (2 * ASZ + 2 * BSZ) // 8960 floats = 35840 B
#define GEMM1_SMEM (2 * STAGE_F * 4)

__global__ __launch_bounds__(256)
void gemm1_kernel() {
    extern __shared__ float smem[];

    int tid = threadIdx.x;
    int wid = tid >> 5, lane = tid & 31;
    int g = lane >> 2, c = lane & 3;
    int warp_m = wid >> 2;            // 0..1 -> m offset *32
    int warp_n = wid & 3;             // 0..3 -> n offset *16

    int m0 = blockIdx.y * 64;
    int n0 = blockIdx.x * 64;
    int r  = n0 >> 8;
    int e0 = n0 & 255;

    const float* pAhi = g_pA_hi;
    const float* pAlo = g_pA_lo;
    const float* wbh = g_wb_hi + (size_t)r * (D_ * D_) + e0;
    const float* wbl = g_wb_lo + (size_t)r * (D_ * D_) + e0;

    unsigned sbase = (unsigned)__cvta_generic_to_shared(smem);

    float acc[2][2][4] = {};

    auto issue_stage = [&](int s, int k0) {
        unsigned st = sbase + (unsigned)(s * STAGE_F * 4);
#pragma unroll
        for (int i = 0; i < 2; ++i) {
            int op = tid + i * 256;          // 0..511
            int row = op >> 3, ch = op & 7;  // A: 64 rows x 8 chunks
            unsigned da = st + (unsigned)((row * A_PITCH + ch * 4) * 4);
            const float* sa = pAhi + (size_t)(m0 + row) * D_ + k0 + ch * 4;
            asm volatile("cp.async.cg.shared.global [%0], [%1], 16;"
                         :: "r"(da), "l"(sa) : "memory");
            unsigned da2 = da + (unsigned)(ASZ * 4);
            const float* sa2 = pAlo + (size_t)(m0 + row) * D_ + k0 + ch * 4;
            asm volatile("cp.async.cg.shared.global [%0], [%1], 16;"
                         :: "r"(da2), "l"(sa2) : "memory");
            int rk = op >> 4, chb = op & 15; // B: 32 k-rows x 16 chunks
            unsigned db = st + (unsigned)((2 * ASZ + rk * B_PITCH + chb * 4) * 4);
            const float* sb = wbh + (size_t)(k0 + rk) * D_ + chb * 4;
            asm volatile("cp.async.cg.shared.global [%0], [%1], 16;"
                         :: "r"(db), "l"(sb) : "memory");
            unsigned db2 = db + (unsigned)(BSZ * 4);
            const float* sb2 = wbl + (size_t)(k0 + rk) * D_ + chb * 4;
            asm volatile("cp.async.cg.shared.global [%0], [%1], 16;"
                         :: "r"(db2), "l"(sb2) : "memory");
        }
        asm volatile("cp.async.commit_group;" ::: "memory");
    };

    issue_stage(0, 0);
    asm volatile("cp.async.wait_group 0;" ::: "memory");
    __syncthreads();

#pragma unroll
    for (int it = 0; it < 8; ++it) {
        int s = it & 1;
        if (it < 7) issue_stage(1 - s, (it + 1) * 32);

        const float* Ah = smem + s * STAGE_F;
        const float* Al = Ah + ASZ;
        const float* Bh = smem + s * STAGE_F + 2 * ASZ;
        const float* Bl = Bh + BSZ;

#pragma unroll
        for (int k8 = 0; k8 < 4; ++k8) {
            int kc = k8 * 8 + c;
            uint32_t ah[2][4], al[2][4], bh[2][2], bl[2][2];
#pragma unroll
            for (int mi = 0; mi < 2; ++mi) {
                int rb = warp_m * 32 + mi * 16 + g;
                ah[mi][0] = __float_as_uint(Ah[rb * A_PITCH + kc]);
                ah[mi][1] = __float_as_uint(Ah[(rb + 8) * A_PITCH + kc]);
                ah[mi][2] = __float_as_uint(Ah[rb * A_PITCH + kc + 4]);
                ah[mi][3] = __float_as_uint(Ah[(rb + 8) * A_PITCH + kc + 4]);
                al[mi][0] = __float_as_uint(Al[rb * A_PITCH + kc]);
                al[mi][1] = __float_as_uint(Al[(rb + 8) * A_PITCH + kc]);
                al[mi][2] = __float_as_uint(Al[rb * A_PITCH + kc + 4]);
                al[mi][3] = __float_as_uint(Al[(rb + 8) * A_PITCH + kc + 4]);
            }
#pragma unroll
            for (int ni = 0; ni < 2; ++ni) {
                int nb = warp_n * 16 + ni * 8 + g;
                bh[ni][0] = __float_as_uint(Bh[kc * B_PITCH + nb]);
                bh[ni][1] = __float_as_uint(Bh[(kc + 4) * B_PITCH + nb]);
                bl[ni][0] = __float_as_uint(Bl[kc * B_PITCH + nb]);
                bl[ni][1] = __float_as_uint(Bl[(kc + 4) * B_PITCH + nb]);
            }
#pragma unroll
            for (int mi = 0; mi < 2; ++mi)
#pragma unroll
                for (int ni = 0; ni < 2; ++ni) {
                    MMA_TF32(acc[mi][ni], ah[mi], bh[ni]);
                    MMA_TF32(acc[mi][ni], ah[mi], bl[ni]);
                    MMA_TF32(acc[mi][ni], al[mi], bh[ni]);
                }
        }

        if (it < 7) asm volatile("cp.async.wait_group 0;" ::: "memory");
        __syncthreads();
    }

    // Epilogue: split T1 into tf32 hi/lo and store both.
#pragma unroll
    for (int mi = 0; mi < 2; ++mi)
#pragma unroll
        for (int ni = 0; ni < 2; ++ni) {
            int row = m0 + warp_m * 32 + mi * 16 + g;
            int col = n0 + warp_n * 16 + ni * 8 + 2 * c;
            float v0 = acc[mi][ni][0], v1 = acc[mi][ni][1];
            float v2 = acc[mi][ni][2], v3 = acc[mi][ni][3];
            float h0 = tf32r(v0), h1 = tf32r(v1), h2 = tf32r(v2), h3 = tf32r(v3);
            *(float2*)&g_T1hi[(size_t)row * N1 + col] = make_float2(h0, h1);
            *(float2*)&g_T1lo[(size_t)row * N1 + col] =
                make_float2(tf32r(v0 - h0), tf32r(v1 - h1));
            *(float2*)&g_T1hi[(size_t)(row + 8) * N1 + col] = make_float2(h2, h3);
            *(float2*)&g_T1lo[(size_t)(row + 8) * N1 + col] =
                make_float2(tf32r(v2 - h2), tf32r(v3 - h3));
        }
}

// ---------------------------------------------------------------------------
// Kernel 3: GEMM2 on tensor cores (3xTF32) + fused score epilogue.
// Identical math/fragments to R14; pipeline deepened to 4 stages with
// cp.async.wait_group 2 (3 stages in flight) so stage-arrival latency is
// hidden under ~3 stages of MMA compute (grid=96 -> 1 block/SM, no
// inter-block overlap available; R14's depth-2/wait-0 exposed the full
// latency every chunk -> 16.7us at 12% on every pipe).
// ---------------------------------------------------------------------------
#define G2_PITCH 36
#define G2_TILE (64 * G2_PITCH)       // 2304 floats
#define G2_STAGE (4 * G2_TILE)        // 9216 floats = 36864 B
#define G2_NSTAGE 4
#define GEMM2_SMEM (G2_NSTAGE * G2_STAGE * 4) // 147456 B

__global__ __launch_bounds__(256)
void gemm2_kernel(const float* __restrict__ bias,
                  const int* __restrict__ ph,
                  const int* __restrict__ pt,
                  float* __restrict__ out) {
    extern __shared__ float smem[];

    int bid = blockIdx.x;                 // b*12 + r
    int b = bid / R_;
    int r = bid - b * R_;

    int tid = threadIdx.x;
    int wid = tid >> 5, lane = tid & 31;
    int g = lane >> 2, c = lane & 3;
    int warp_m = wid >> 2;            // 0..1 -> s offset *32
    int warp_n = wid & 3;             // 0..3 -> t offset *16

    const float* Ahg = g_T1hi + (size_t)b * S_ * N1 + r * D_;   // row s: +s*N1
    const float* Alg = g_T1lo + (size_t)b * S_ * N1 + r * D_;
    const float* Bhg = g_pA_hi + (size_t)b * S_ * D_;           // row t: +t*256
    const float* Blg = g_pA_lo + (size_t)b * S_ * D_;

    unsigned sbase = (unsigned)__cvta_generic_to_shared(smem);

    float acc[2][2][4] = {};

    // 4 tiles x 64 rows x 8 16B-chunks = 2048 cp.async / 256 threads.
    auto issue_stage = [&](int s, int k0) {
        unsigned st = sbase + (unsigned)(s * G2_STAGE * 4);
#pragma unroll
        for (int i = 0; i < 2; ++i) {
            int op = tid + i * 256;          // 0..511
            int row = op >> 3, ch = op & 7;
            unsigned d0 = st + (unsigned)((row * G2_PITCH + ch * 4) * 4);
            const float* s0 = Ahg + (size_t)row * N1 + k0 + ch * 4;
            asm volatile("cp.async.cg.shared.global [%0], [%1], 16;"
                         :: "r"(d0), "l"(s0) : "memory");
            unsigned d1 = d0 + (unsigned)(G2_TILE * 4);
            const float* s1 = Alg + (size_t)row * N1 + k0 + ch * 4;
            asm volatile("cp.async.cg.shared.global [%0], [%1], 16;"
                         :: "r"(d1), "l"(s1) : "memory");
            unsigned d2 = d1 + (unsigned)(G2_TILE * 4);
            const float* s2 = Bhg + (size_t)row * D_ + k0 + ch * 4;
            asm volatile("cp.async.cg.shared.global [%0], [%1], 16;"
                         :: "r"(d2), "l"(s2) : "memory");
            unsigned d3 = d2 + (unsigned)(G2_TILE * 4);
            const float* s3 = Blg + (size_t)row * D_ + k0 + ch * 4;
            asm volatile("cp.async.cg.shared.global [%0], [%1], 16;"
                         :: "r"(d3), "l"(s3) : "memory");
        }
        asm volatile("cp.async.commit_group;" ::: "memory");
    };

    // Prologue: fill 3 of 4 stages.
    issue_stage(0, 0);
    issue_stage(1, 32);
    issue_stage(2, 64);
    asm volatile("cp.async.wait_group 2;" ::: "memory");   // stage 0 ready
    __syncthreads();

#pragma unroll
    for (int it = 0; it < 8; ++it) {
        int s = it & 3;
        // Issue stage it+3 into slot (it+3)&3 = (it-1)&3 (freed by last sync).
        if (it + 3 < 8) issue_stage((it + 3) & 3, (it + 3) * 32);

        const float* Ah = smem + s * G2_STAGE;
        const float* Al = Ah + G2_TILE;
        const float* Bh = Al + G2_TILE;
        const float* Bl = Bh + G2_TILE;

#pragma unroll
        for (int k8 = 0; k8 < 4; ++k8) {
            int kc = k8 * 8 + c;
            uint32_t ah[2][4], al[2][4], bh[2][2], bl[2][2];
#pragma unroll
            for (int mi = 0; mi < 2; ++mi) {
                int rb = warp_m * 32 + mi * 16 + g;
                ah[mi][0] = __float_as_uint(Ah[rb * G2_PITCH + kc]);
                ah[mi][1] = __float_as_uint(Ah[(rb + 8) * G2_PITCH + kc]);
                ah[mi][2] = __float_as_uint(Ah[rb * G2_PITCH + kc + 4]);
                ah[mi][3] = __float_as_uint(Ah[(rb + 8) * G2_PITCH + kc + 4]);
                al[mi][0] = __float_as_uint(Al[rb * G2_PITCH + kc]);
                al[mi][1] = __float_as_uint(Al[(rb + 8) * G2_PITCH + kc]);
                al[mi][2] = __float_as_uint(Al[rb * G2_PITCH + kc + 4]);
                al[mi][3] = __float_as_uint(Al[(rb + 8) * G2_PITCH + kc + 4]);
            }
#pragma unroll
            for (int ni = 0; ni < 2; ++ni) {
                int nb = warp_n * 16 + ni * 8 + g;
                bh[ni][0] = __float_as_uint(Bh[nb * G2_PITCH + kc]);
                bh[ni][1] = __float_as_uint(Bh[nb * G2_PITCH + kc + 4]);
                bl[ni][0] = __float_as_uint(Bl[nb * G2_PITCH + kc]);
                bl[ni][1] = __float_as_uint(Bl[nb * G2_PITCH + kc + 4]);
            }
#pragma unroll
            for (int mi = 0; mi < 2; ++mi)
#pragma unroll
                for (int ni = 0; ni < 2; ++ni) {
                    MMA_TF32(acc[mi][ni], ah[mi], bh[ni]);
                    MMA_TF32(acc[mi][ni], ah[mi], bl[ni]);
                    MMA_TF32(acc[mi][ni], al[mi], bh[ni]);
                }
        }

        // Ensure stage it+1 has arrived before next iteration computes it.
        asm volatile("cp.async.wait_group 2;" ::: "memory");
        __syncthreads();
    }

    // Park G tile in smem (pipeline stages are dead now), then pair gather.
    float* sg = smem;                 // 64x64 = 16 KB
#pragma unroll
    for (int mi = 0; mi < 2; ++mi)
#pragma unroll
        for (int ni = 0; ni < 2; ++ni) {
            int row = warp_m * 32 + mi * 16 + g;
            int col = warp_n * 16 + ni * 8 + 2 * c;
            sg[row * 64 + col]       = acc[mi][ni][0];
            sg[row * 64 + col + 1]   = acc[mi][ni][1];
            sg[(row + 8) * 64 + col]     = acc[mi][ni][2];
            sg[(row + 8) * 64 + col + 1] = acc[mi][ni][3];
        }
    __syncthreads();

    // Fused pair-score gather: 1024 pairs / 256 threads = 4 each.
    float bv = bias[r];
    const float* Lb = g_L + (size_t)b * S_ * (2 * R_);
    const int* phb = ph + (b << 10);
    const int* ptb = pt + (b << 10);
#pragma unroll
    for (int i = 0; i < 4; ++i) {
        int p = tid + i * 256;
        int h = phb[p];
        int t = ptb[p];
        float sc = sg[h * 64 + t] + Lb[h * 24 + r] + Lb[t * 24 + 12 + r] + bv;
        out[(size_t)((b << 10) + p) * R_ + r] = 1.f / (1.f + __expf(-sc));
    }
}

// ---------------------------------------------------------------------------
// Launch.  Inputs in metadata order:
// 0 encoded f32 [8,512,256]   1 W_linear f32 [512,12]   2 b_linear f32 [12]
// 3 W_bilinear f32 [12,256,256]
// 4 span_starts i32 [8,64]    5 span_lens i32 [8,64]
// 6 pair_head i32 [8,1024]    7 pair_tail i32 [8,1024]
// Output f32 [8,1024,12].
// ---------------------------------------------------------------------------
extern "C" void kernel_launch(void* const* d_in, const int* in_sizes, int n_in,
                              void* d_out, int out_size) {
    const float* enc = (const float*)d_in[0];
    const float* Wl  = (const float*)d_in[1];
    const float* bl  = (const float*)d_in[2];
    const float* Wb  = (const float*)d_in[3];
    const int* sst   = (const int*)d_in[4];
    const int* sln   = (const int*)d_in[5];
    const int* ph    = (const int*)d_in[6];
    const int* pt    = (const int*)d_in[7];
    float* out = (float*)d_out;

    cudaFuncSetAttribute(gemm1_kernel,
                         cudaFuncAttributeMaxDynamicSharedMemorySize,
                         GEMM1_SMEM);
    cudaFuncSetAttribute(gemm2_kernel,
                         cudaFuncAttributeMaxDynamicSharedMemorySize,
                         GEMM2_SMEM);

    pool_kernel<<<B_ * S_, 256>>>(enc, Wl, sst, sln);
    split_wb_kernel<<<256, 256>>>(Wb);
    gemm1_kernel<<<dim3(N1 / 64, (B_ * S_) / 64), 256, GEMM1_SMEM>>>();
    gemm2_kernel<<<B_ * R_, 256, GEMM2_SMEM>>>(bl, ph, pt, out);
}